// round 1
// baseline (speedup 1.0000x reference)
#include <cuda_runtime.h>
#include <math.h>

// ---------------------------------------------------------------------------
// FuseView: B=8, T=128, J=17, Cp=32, N=4
// ---------------------------------------------------------------------------

namespace fv {
constexpr int J_   = 17;
constexpr int C_   = 544;    // J*Cp
constexpr int CIN_ = 1088;   // 2*C
constexpr int BT_  = 1024;   // B*T
constexpr int P4_  = 4096;   // BT*N
constexpr int P16_ = 16384;  // BT*N*N
constexpr int PCH_ = 34;     // 2*J

constexpr size_t SZ_F   = (size_t)C_ * P4_;
constexpr size_t SZ_P2  = (size_t)PCH_ * P4_;
constexpr size_t SZ_A   = (size_t)CIN_ * P4_;
constexpr size_t SZ_H   = (size_t)CIN_ * P16_;
constexpr size_t SZ_AG  = (size_t)C_ * P16_;
constexpr size_t SZ_AT  = (size_t)P16_;
constexpr size_t SZ_WT  = (size_t)C_ * C_;
constexpr size_t SZ_SBN = (size_t)5 * 2 * CIN_;

constexpr size_t OFF_F    = 0;
constexpr size_t OFF_P2   = OFF_F + SZ_F;
constexpr size_t OFF_A    = OFF_P2 + SZ_P2;
constexpr size_t OFF_B    = OFF_A + SZ_A;
constexpr size_t OFF_PP   = OFF_B + SZ_A;
constexpr size_t OFF_H0   = OFF_PP + SZ_A;
constexpr size_t OFF_H1   = OFF_H0 + SZ_H;
constexpr size_t OFF_H2   = OFF_H1 + SZ_H;
constexpr size_t OFF_G    = OFF_H2 + SZ_H;
constexpr size_t OFF_AG   = OFF_G + SZ_H;
constexpr size_t OFF_ATTL = OFF_AG + SZ_AG;
constexpr size_t OFF_ATTS = OFF_ATTL + SZ_AT;
constexpr size_t OFF_FS   = OFF_ATTS + SZ_AT;
constexpr size_t OFF_FT   = OFF_FS + SZ_F;
constexpr size_t OFF_W0T  = OFF_FT + SZ_F;
constexpr size_t OFF_W1T  = OFF_W0T + SZ_WT;
constexpr size_t OFF_SBN  = OFF_W1T + SZ_WT;
constexpr size_t TOTAL    = OFF_SBN + SZ_SBN;
}  // namespace fv

__device__ float g_BUF[fv::TOTAL];

using namespace fv;

// ---------------------------------------------------------------------------
// BN fold: s = g * rsqrt(v+eps), t = b - m*s  for 5 BN layers
// ---------------------------------------------------------------------------
__global__ void k_bn_fold(const float* __restrict__ b0, const float* __restrict__ b1,
                          const float* __restrict__ b2, const float* __restrict__ b3,
                          const float* __restrict__ b4, float* __restrict__ sbn) {
    int idx = blockIdx.x * blockDim.x + threadIdx.x;
    if (idx >= 5 * CIN_) return;
    int which = idx / CIN_, c = idx % CIN_;
    const float* bn = which == 0 ? b0 : which == 1 ? b1 : which == 2 ? b2 : which == 3 ? b3 : b4;
    float g = bn[c], bb = bn[CIN_ + c], m = bn[2 * CIN_ + c], v = bn[3 * CIN_ + c];
    float s = g * rsqrtf(v + 1e-5f);
    sbn[which * 2 * CIN_ + c]        = s;
    sbn[which * 2 * CIN_ + CIN_ + c] = bb - m * s;
}

// ---------------------------------------------------------------------------
// Transpose W[0], W[1] (544x544, stored W[w][c][d]) -> WT[w][d][c]
// ---------------------------------------------------------------------------
__global__ void k_wT(const float* __restrict__ W, float* __restrict__ w0t,
                     float* __restrict__ w1t) {
    int idx = blockIdx.x * blockDim.x + threadIdx.x;
    if (idx >= 2 * C_ * C_) return;
    int w = idx / (C_ * C_);
    int r = idx % (C_ * C_);
    int d = r / C_, c = r % C_;
    float v = W[(size_t)w * C_ * C_ + (size_t)c * C_ + d];
    (w == 0 ? w0t : w1t)[(size_t)d * C_ + c] = v;
}

// ---------------------------------------------------------------------------
// f[c][p4] from x (B,T,J,Cp,N);  c = j*32+cp, p4 = bt*4+n
// ---------------------------------------------------------------------------
__global__ void k_build_f(const float* __restrict__ x, float* __restrict__ F) {
    int idx = blockIdx.x * blockDim.x + threadIdx.x;
    if (idx >= C_ * P4_) return;
    int c = idx / P4_, p = idx % P4_;
    int bt = p >> 2, n = p & 3;
    F[idx] = x[((size_t)bt * C_ + c) * 4 + n];
}

// p2[k][p4] from pos_2d (B,T,J,2,N); k = j*2+cc
__global__ void k_build_p(const float* __restrict__ pos, float* __restrict__ P2) {
    int idx = blockIdx.x * blockDim.x + threadIdx.x;
    if (idx >= PCH_ * P4_) return;
    int k = idx / P4_, p = idx % P4_;
    int bt = p >> 2, n = p & 3;
    P2[idx] = pos[((size_t)bt * PCH_ + k) * 4 + n];
}

// ---------------------------------------------------------------------------
// PP = w_pos (1088x34) @ P2 (34x4096)
// ---------------------------------------------------------------------------
__global__ void k_pos(const float* __restrict__ wpos, const float* __restrict__ P2,
                      float* __restrict__ PP) {
    int idx = blockIdx.x * blockDim.x + threadIdx.x;
    if (idx >= CIN_ * P4_) return;
    int o = idx / P4_, p = idx % P4_;
    float acc = 0.f;
#pragma unroll
    for (int k = 0; k < PCH_; k++) acc += wpos[o * PCH_ + k] * P2[k * P4_ + p];
    PP[idx] = acc;
}

// ---------------------------------------------------------------------------
// h0 assembly: h0[o, bt*16+i*4+j] = relu(s*(A[o,bt*4+i]+Bv[o,bt*4+j])+t)
//                                   + PP[o,bt*4+i] - PP[o,bt*4+j] + b_pos[o]
// ---------------------------------------------------------------------------
__global__ void k_h0(const float* __restrict__ A, const float* __restrict__ Bv,
                     const float* __restrict__ PP, const float* __restrict__ bpos,
                     const float* __restrict__ sbn, float* __restrict__ H0) {
    int idx = blockIdx.x * blockDim.x + threadIdx.x;
    if (idx >= CIN_ * P16_) return;
    int o = idx / P16_, col = idx % P16_;
    int bt = col >> 4, ij = col & 15;
    int i = ij >> 2, j = ij & 3;
    int ci = bt * 4 + i, cj = bt * 4 + j;
    float s = sbn[o], t = sbn[CIN_ + o];
    float v = fmaxf(fmaf(s, A[(size_t)o * P4_ + ci] + Bv[(size_t)o * P4_ + cj], t), 0.f);
    H0[idx] = v + PP[(size_t)o * P4_ + ci] - PP[(size_t)o * P4_ + cj] + bpos[o];
}

// ---------------------------------------------------------------------------
// SGEMM: C(MxN) = A(MxK, row stride lda) @ B(KxN)
// EPI 0: plain   1: relu(s*acc+t)   2: res + relu(s*acc+t)   3: acc + bias(sv)
// ---------------------------------------------------------------------------
template <int EPI>
__global__ __launch_bounds__(256, 2) void sgemm(const float* __restrict__ A, int lda,
                                                const float* __restrict__ B,
                                                float* __restrict__ C, int M, int N, int K,
                                                const float* __restrict__ sv,
                                                const float* __restrict__ tv,
                                                const float* __restrict__ res) {
    constexpr int BM = 128, BN = 128, BK = 8, TM = 8, TN = 8;
    __shared__ float As[BK][BM];
    __shared__ float Bs[BK][BN];

    const int tid = threadIdx.x;
    const int bx = blockIdx.x, by = blockIdx.y;
    const int tx = tid % 16, ty = tid / 16;

    const int aRow = tid >> 1;
    const int aCol = (tid & 1) << 2;
    const int bRow = tid >> 5;
    const int bCol = (tid & 31) << 2;

    const int gARow = by * BM + aRow;
    const bool aValid = gARow < M;
    const float* Aptr = A + (size_t)(aValid ? gARow : 0) * lda + aCol;
    const float* Bptr = B + (size_t)bRow * N + (size_t)bx * BN + bCol;

    float acc[TM][TN];
#pragma unroll
    for (int i = 0; i < TM; i++)
#pragma unroll
        for (int j = 0; j < TN; j++) acc[i][j] = 0.f;

    for (int k0 = 0; k0 < K; k0 += BK) {
        float4 av = make_float4(0.f, 0.f, 0.f, 0.f);
        if (aValid) av = *reinterpret_cast<const float4*>(Aptr + k0);
        As[aCol + 0][aRow] = av.x;
        As[aCol + 1][aRow] = av.y;
        As[aCol + 2][aRow] = av.z;
        As[aCol + 3][aRow] = av.w;
        float4 bv = *reinterpret_cast<const float4*>(Bptr + (size_t)k0 * N);
        *reinterpret_cast<float4*>(&Bs[bRow][bCol]) = bv;
        __syncthreads();

#pragma unroll
        for (int k = 0; k < BK; k++) {
            float4 a0 = *reinterpret_cast<const float4*>(&As[k][ty * TM]);
            float4 a1 = *reinterpret_cast<const float4*>(&As[k][ty * TM + 4]);
            float4 b0 = *reinterpret_cast<const float4*>(&Bs[k][tx * TN]);
            float4 b1 = *reinterpret_cast<const float4*>(&Bs[k][tx * TN + 4]);
            float ra[TM] = {a0.x, a0.y, a0.z, a0.w, a1.x, a1.y, a1.z, a1.w};
            float rb[TN] = {b0.x, b0.y, b0.z, b0.w, b1.x, b1.y, b1.z, b1.w};
#pragma unroll
            for (int i = 0; i < TM; i++)
#pragma unroll
                for (int j = 0; j < TN; j++) acc[i][j] = fmaf(ra[i], rb[j], acc[i][j]);
        }
        __syncthreads();
    }

#pragma unroll
    for (int i = 0; i < TM; i++) {
        int r = by * BM + ty * TM + i;
        if (r >= M) continue;
        size_t rowOff = (size_t)r * N + (size_t)bx * BN + tx * TN;
        float s = 0.f, t = 0.f;
        if (EPI == 1 || EPI == 2) { s = sv[r]; t = tv[r]; }
        if (EPI == 3) { t = sv[r]; }
#pragma unroll
        for (int j = 0; j < TN; j++) {
            float v = acc[i][j];
            if (EPI == 1) v = fmaxf(fmaf(s, v, t), 0.f);
            if (EPI == 2) v = res[rowOff + j] + fmaxf(fmaf(s, v, t), 0.f);
            if (EPI == 3) v = v + t;
            C[rowOff + j] = v;
        }
    }
}

// ---------------------------------------------------------------------------
// att logits: l[p] = b + sum_c w[c] * G[c][p]
// ---------------------------------------------------------------------------
__global__ void k_attlogit(const float* __restrict__ w, const float* __restrict__ b,
                           const float* __restrict__ G, float* __restrict__ L) {
    int p = blockIdx.x * blockDim.x + threadIdx.x;
    if (p >= P16_) return;
    float acc = b[0];
#pragma unroll 8
    for (int c = 0; c < CIN_; c++) acc += w[c] * G[(size_t)c * P16_ + p];
    L[p] = acc;
}

// softmax over j (rows of 4): row r in [0, 4096)
__global__ void k_softmax(const float* __restrict__ L, float* __restrict__ S) {
    int r = blockIdx.x * blockDim.x + threadIdx.x;
    if (r >= P4_) return;
    float l0 = L[r * 4 + 0], l1 = L[r * 4 + 1], l2 = L[r * 4 + 2], l3 = L[r * 4 + 3];
    float m = fmaxf(fmaxf(l0, l1), fmaxf(l2, l3));
    float e0 = expf(l0 - m), e1 = expf(l1 - m), e2 = expf(l2 - m), e3 = expf(l3 - m);
    float inv = 1.f / (e0 + e1 + e2 + e3);
    S[r * 4 + 0] = e0 * inv;
    S[r * 4 + 1] = e1 * inv;
    S[r * 4 + 2] = e2 * inv;
    S[r * 4 + 3] = e3 * inv;
}

// ---------------------------------------------------------------------------
// final fuse + output permute: out[bt*2176 + d*4 + i]
// ---------------------------------------------------------------------------
__global__ void k_fuse(const float* __restrict__ F, const float* __restrict__ FS,
                       const float* __restrict__ FT, const float* __restrict__ AG,
                       const float* __restrict__ S, float* __restrict__ out) {
    int idx = blockIdx.x * blockDim.x + threadIdx.x;
    if (idx >= BT_ * 2176) return;
    int bt = idx / 2176;
    int rem = idx % 2176;
    int d = rem >> 2, i = rem & 3;
    int ri = bt * 4 + i;
    float acc = F[(size_t)d * P4_ + ri];
#pragma unroll
    for (int j = 0; j < 4; j++) {
        float a = S[ri * 4 + j];
        if (j == i) {
            acc = fmaf(FS[(size_t)d * P4_ + ri], a, acc);
        } else {
            float tv = FT[(size_t)d * P4_ + bt * 4 + j];
            float ag = AG[(size_t)d * P16_ + bt * 16 + i * 4 + j];
            acc = fmaf(tv * ag, a, acc);
        }
    }
    out[idx] = acc;
}

// ---------------------------------------------------------------------------
extern "C" void kernel_launch(void* const* d_in, const int* in_sizes, int n_in,
                              void* d_out, int out_size) {
    const float* x      = (const float*)d_in[0];
    const float* pos2d  = (const float*)d_in[1];
    const float* w_pos  = (const float*)d_in[2];
    const float* b_pos  = (const float*)d_in[3];
    const float* w_e    = (const float*)d_in[4];
    const float* bn_e   = (const float*)d_in[5];
    const float* w1     = (const float*)d_in[6];
    const float* bn1    = (const float*)d_in[7];
    const float* w2     = (const float*)d_in[8];
    const float* bn2    = (const float*)d_in[9];
    const float* w_ag   = (const float*)d_in[10];
    const float* bn_ag  = (const float*)d_in[11];
    const float* w_ag_s = (const float*)d_in[12];
    const float* b_ag_s = (const float*)d_in[13];
    const float* w_att  = (const float*)d_in[14];
    const float* bn_att = (const float*)d_in[15];
    const float* w_att_s= (const float*)d_in[16];
    const float* b_att_s= (const float*)d_in[17];
    const float* Wsm    = (const float*)d_in[18];
    float* out = (float*)d_out;

    float* base = nullptr;
    cudaGetSymbolAddress((void**)&base, g_BUF);

    float* F    = base + OFF_F;
    float* P2   = base + OFF_P2;
    float* A    = base + OFF_A;
    float* Bv   = base + OFF_B;
    float* PP   = base + OFF_PP;
    float* H0   = base + OFF_H0;
    float* H1   = base + OFF_H1;
    float* H2   = base + OFF_H2;
    float* G    = base + OFF_G;
    float* AG   = base + OFF_AG;
    float* ATTL = base + OFF_ATTL;
    float* ATTS = base + OFF_ATTS;
    float* FS   = base + OFF_FS;
    float* FT   = base + OFF_FT;
    float* W0T  = base + OFF_W0T;
    float* W1T  = base + OFF_W1T;
    float* SBN  = base + OFF_SBN;

    // prep
    k_bn_fold<<<(5 * CIN_ + 255) / 256, 256>>>(bn_e, bn1, bn2, bn_ag, bn_att, SBN);
    k_wT<<<(2 * C_ * C_ + 255) / 256, 256>>>(Wsm, W0T, W1T);
    k_build_f<<<(C_ * P4_ + 255) / 256, 256>>>(x, F);
    k_build_p<<<(PCH_ * P4_ + 255) / 256, 256>>>(pos2d, P2);

    // layer 1 (separable): A = We[:, :C] @ f ; Bv = We[:, C:] @ f
    dim3 g1(P4_ / 128, (CIN_ + 127) / 128);
    sgemm<0><<<g1, 256>>>(w_e, CIN_, F, A, CIN_, P4_, C_, nullptr, nullptr, nullptr);
    sgemm<0><<<g1, 256>>>(w_e + C_, CIN_, F, Bv, CIN_, P4_, C_, nullptr, nullptr, nullptr);
    k_pos<<<(CIN_ * P4_ + 255) / 256, 256>>>(w_pos, P2, PP);
    k_h0<<<(CIN_ * P16_ + 255) / 256, 256>>>(A, Bv, PP, b_pos, SBN /*bn_expand*/, H0);

    // trunk
    dim3 g2(P16_ / 128, (CIN_ + 127) / 128);
    sgemm<1><<<g2, 256>>>(w1, CIN_, H0, H1, CIN_, P16_, CIN_,
                          SBN + 1 * 2 * CIN_, SBN + 1 * 2 * CIN_ + CIN_, nullptr);
    sgemm<2><<<g2, 256>>>(w2, CIN_, H1, H2, CIN_, P16_, CIN_,
                          SBN + 2 * 2 * CIN_, SBN + 2 * 2 * CIN_ + CIN_, H0);

    // aggregation branch
    sgemm<1><<<g2, 256>>>(w_ag, CIN_, H2, G, CIN_, P16_, CIN_,
                          SBN + 3 * 2 * CIN_, SBN + 3 * 2 * CIN_ + CIN_, nullptr);
    dim3 g3(P16_ / 128, (C_ + 127) / 128);
    sgemm<3><<<g3, 256>>>(w_ag_s, CIN_, G, AG, C_, P16_, CIN_, b_ag_s, nullptr, nullptr);

    // attention branch (reuse G)
    sgemm<1><<<g2, 256>>>(w_att, CIN_, H2, G, CIN_, P16_, CIN_,
                          SBN + 4 * 2 * CIN_, SBN + 4 * 2 * CIN_ + CIN_, nullptr);
    k_attlogit<<<(P16_ + 255) / 256, 256>>>(w_att_s, b_att_s, G, ATTL);
    k_softmax<<<(P4_ + 255) / 256, 256>>>(ATTL, ATTS);

    // self / transfer projections
    dim3 g4(P4_ / 128, (C_ + 127) / 128);
    sgemm<0><<<g4, 256>>>(W0T, C_, F, FS, C_, P4_, C_, nullptr, nullptr, nullptr);
    sgemm<0><<<g4, 256>>>(W1T, C_, F, FT, C_, P4_, C_, nullptr, nullptr, nullptr);

    // fuse + permute to output
    k_fuse<<<(BT_ * 2176 + 255) / 256, 256>>>(F, FS, FT, AG, ATTS, out);
}

// round 2
// speedup vs baseline: 1.0020x; 1.0020x over previous
#include <cuda_runtime.h>
#include <math.h>

// ---------------------------------------------------------------------------
// FuseView: B=8, T=128, J=17, Cp=32, N=4
// ---------------------------------------------------------------------------

namespace fv {
constexpr int J_   = 17;
constexpr int C_   = 544;    // J*Cp
constexpr int CIN_ = 1088;   // 2*C
constexpr int BT_  = 1024;   // B*T
constexpr int P4_  = 4096;   // BT*N
constexpr int P16_ = 16384;  // BT*N*N
constexpr int PCH_ = 34;     // 2*J

constexpr size_t SZ_F   = (size_t)C_ * P4_;
constexpr size_t SZ_P2  = (size_t)PCH_ * P4_;
constexpr size_t SZ_A   = (size_t)CIN_ * P4_;
constexpr size_t SZ_H   = (size_t)CIN_ * P16_;
constexpr size_t SZ_AG  = (size_t)C_ * P16_;
constexpr size_t SZ_AT  = (size_t)P16_;
constexpr size_t SZ_WT  = (size_t)C_ * C_;
constexpr size_t SZ_SBN = (size_t)5 * 2 * CIN_;

constexpr size_t OFF_F    = 0;
constexpr size_t OFF_P2   = OFF_F + SZ_F;
constexpr size_t OFF_A    = OFF_P2 + SZ_P2;
constexpr size_t OFF_B    = OFF_A + SZ_A;
constexpr size_t OFF_PP   = OFF_B + SZ_A;
constexpr size_t OFF_H0   = OFF_PP + SZ_A;
constexpr size_t OFF_H1   = OFF_H0 + SZ_H;
constexpr size_t OFF_H2   = OFF_H1 + SZ_H;
constexpr size_t OFF_G    = OFF_H2 + SZ_H;
constexpr size_t OFF_AG   = OFF_G + SZ_H;
constexpr size_t OFF_ATTL = OFF_AG + SZ_AG;
constexpr size_t OFF_ATTS = OFF_ATTL + SZ_AT;
constexpr size_t OFF_FS   = OFF_ATTS + SZ_AT;
constexpr size_t OFF_FT   = OFF_FS + SZ_F;
constexpr size_t OFF_W0T  = OFF_FT + SZ_F;
constexpr size_t OFF_W1T  = OFF_W0T + SZ_WT;
constexpr size_t OFF_SBN  = OFF_W1T + SZ_WT;
constexpr size_t TOTAL    = OFF_SBN + SZ_SBN;
}  // namespace fv

__device__ float g_BUF[fv::TOTAL];

using namespace fv;

// ---------------------------------------------------------------------------
// BN fold: s = g * rsqrt(v+eps), t = b - m*s  for 5 BN layers
// ---------------------------------------------------------------------------
__global__ void k_bn_fold(const float* __restrict__ b0, const float* __restrict__ b1,
                          const float* __restrict__ b2, const float* __restrict__ b3,
                          const float* __restrict__ b4, float* __restrict__ sbn) {
    int idx = blockIdx.x * blockDim.x + threadIdx.x;
    if (idx >= 5 * CIN_) return;
    int which = idx / CIN_, c = idx % CIN_;
    const float* bn = which == 0 ? b0 : which == 1 ? b1 : which == 2 ? b2 : which == 3 ? b3 : b4;
    float g = bn[c], bb = bn[CIN_ + c], m = bn[2 * CIN_ + c], v = bn[3 * CIN_ + c];
    float s = g * rsqrtf(v + 1e-5f);
    sbn[which * 2 * CIN_ + c]        = s;
    sbn[which * 2 * CIN_ + CIN_ + c] = bb - m * s;
}

// ---------------------------------------------------------------------------
// Transpose W[0], W[1] (544x544, stored W[w][c][d]) -> WT[w][d][c]
// ---------------------------------------------------------------------------
__global__ void k_wT(const float* __restrict__ W, float* __restrict__ w0t,
                     float* __restrict__ w1t) {
    int idx = blockIdx.x * blockDim.x + threadIdx.x;
    if (idx >= 2 * C_ * C_) return;
    int w = idx / (C_ * C_);
    int r = idx % (C_ * C_);
    int d = r / C_, c = r % C_;
    float v = W[(size_t)w * C_ * C_ + (size_t)c * C_ + d];
    (w == 0 ? w0t : w1t)[(size_t)d * C_ + c] = v;
}

// ---------------------------------------------------------------------------
// f[c][p4] from x (B,T,J,Cp,N);  c = j*32+cp, p4 = bt*4+n
// ---------------------------------------------------------------------------
__global__ void k_build_f(const float* __restrict__ x, float* __restrict__ F) {
    int idx = blockIdx.x * blockDim.x + threadIdx.x;
    if (idx >= C_ * P4_) return;
    int c = idx / P4_, p = idx % P4_;
    int bt = p >> 2, n = p & 3;
    F[idx] = x[((size_t)bt * C_ + c) * 4 + n];
}

// p2[k][p4] from pos_2d (B,T,J,2,N); k = j*2+cc
__global__ void k_build_p(const float* __restrict__ pos, float* __restrict__ P2) {
    int idx = blockIdx.x * blockDim.x + threadIdx.x;
    if (idx >= PCH_ * P4_) return;
    int k = idx / P4_, p = idx % P4_;
    int bt = p >> 2, n = p & 3;
    P2[idx] = pos[((size_t)bt * PCH_ + k) * 4 + n];
}

// ---------------------------------------------------------------------------
// PP = w_pos (1088x34) @ P2 (34x4096)
// ---------------------------------------------------------------------------
__global__ void k_pos(const float* __restrict__ wpos, const float* __restrict__ P2,
                      float* __restrict__ PP) {
    int idx = blockIdx.x * blockDim.x + threadIdx.x;
    if (idx >= CIN_ * P4_) return;
    int o = idx / P4_, p = idx % P4_;
    float acc = 0.f;
#pragma unroll
    for (int k = 0; k < PCH_; k++) acc += wpos[o * PCH_ + k] * P2[k * P4_ + p];
    PP[idx] = acc;
}

// ---------------------------------------------------------------------------
// h0 assembly: h0[o, bt*16+i*4+j] = relu(s*(A[o,bt*4+i]+Bv[o,bt*4+j])+t)
//                                   + PP[o,bt*4+i] - PP[o,bt*4+j] + b_pos[o]
// ---------------------------------------------------------------------------
__global__ void k_h0(const float* __restrict__ A, const float* __restrict__ Bv,
                     const float* __restrict__ PP, const float* __restrict__ bpos,
                     const float* __restrict__ sbn, float* __restrict__ H0) {
    int idx = blockIdx.x * blockDim.x + threadIdx.x;
    if (idx >= CIN_ * P16_) return;
    int o = idx / P16_, col = idx % P16_;
    int bt = col >> 4, ij = col & 15;
    int i = ij >> 2, j = ij & 3;
    int ci = bt * 4 + i, cj = bt * 4 + j;
    float s = sbn[o], t = sbn[CIN_ + o];
    float v = fmaxf(fmaf(s, A[(size_t)o * P4_ + ci] + Bv[(size_t)o * P4_ + cj], t), 0.f);
    H0[idx] = v + PP[(size_t)o * P4_ + ci] - PP[(size_t)o * P4_ + cj] + bpos[o];
}

// ---------------------------------------------------------------------------
// SGEMM: C(MxN) = A(MxK, row stride lda) @ B(KxN)
// EPI 0: plain   1: relu(s*acc+t)   2: res + relu(s*acc+t)   3: acc + bias(sv)
// ---------------------------------------------------------------------------
template <int EPI>
__global__ __launch_bounds__(256, 2) void sgemm(const float* __restrict__ A, int lda,
                                                const float* __restrict__ B,
                                                float* __restrict__ C, int M, int N, int K,
                                                const float* __restrict__ sv,
                                                const float* __restrict__ tv,
                                                const float* __restrict__ res) {
    constexpr int BM = 128, BN = 128, BK = 8, TM = 8, TN = 8;
    __shared__ float As[BK][BM];
    __shared__ float Bs[BK][BN];

    const int tid = threadIdx.x;
    const int bx = blockIdx.x, by = blockIdx.y;
    const int tx = tid % 16, ty = tid / 16;

    const int aRow = tid >> 1;
    const int aCol = (tid & 1) << 2;
    const int bRow = tid >> 5;
    const int bCol = (tid & 31) << 2;

    const int gARow = by * BM + aRow;
    const bool aValid = gARow < M;
    const float* Aptr = A + (size_t)(aValid ? gARow : 0) * lda + aCol;
    const float* Bptr = B + (size_t)bRow * N + (size_t)bx * BN + bCol;

    float acc[TM][TN];
#pragma unroll
    for (int i = 0; i < TM; i++)
#pragma unroll
        for (int j = 0; j < TN; j++) acc[i][j] = 0.f;

    for (int k0 = 0; k0 < K; k0 += BK) {
        float4 av = make_float4(0.f, 0.f, 0.f, 0.f);
        if (aValid) av = *reinterpret_cast<const float4*>(Aptr + k0);
        As[aCol + 0][aRow] = av.x;
        As[aCol + 1][aRow] = av.y;
        As[aCol + 2][aRow] = av.z;
        As[aCol + 3][aRow] = av.w;
        float4 bv = *reinterpret_cast<const float4*>(Bptr + (size_t)k0 * N);
        *reinterpret_cast<float4*>(&Bs[bRow][bCol]) = bv;
        __syncthreads();

#pragma unroll
        for (int k = 0; k < BK; k++) {
            float4 a0 = *reinterpret_cast<const float4*>(&As[k][ty * TM]);
            float4 a1 = *reinterpret_cast<const float4*>(&As[k][ty * TM + 4]);
            float4 b0 = *reinterpret_cast<const float4*>(&Bs[k][tx * TN]);
            float4 b1 = *reinterpret_cast<const float4*>(&Bs[k][tx * TN + 4]);
            float ra[TM] = {a0.x, a0.y, a0.z, a0.w, a1.x, a1.y, a1.z, a1.w};
            float rb[TN] = {b0.x, b0.y, b0.z, b0.w, b1.x, b1.y, b1.z, b1.w};
#pragma unroll
            for (int i = 0; i < TM; i++)
#pragma unroll
                for (int j = 0; j < TN; j++) acc[i][j] = fmaf(ra[i], rb[j], acc[i][j]);
        }
        __syncthreads();
    }

#pragma unroll
    for (int i = 0; i < TM; i++) {
        int r = by * BM + ty * TM + i;
        if (r >= M) continue;
        size_t rowOff = (size_t)r * N + (size_t)bx * BN + tx * TN;
        float s = 0.f, t = 0.f;
        if (EPI == 1 || EPI == 2) { s = sv[r]; t = tv[r]; }
        if (EPI == 3) { t = sv[r]; }
#pragma unroll
        for (int j = 0; j < TN; j++) {
            float v = acc[i][j];
            if (EPI == 1) v = fmaxf(fmaf(s, v, t), 0.f);
            if (EPI == 2) v = res[rowOff + j] + fmaxf(fmaf(s, v, t), 0.f);
            if (EPI == 3) v = v + t;
            C[rowOff + j] = v;
        }
    }
}

// ---------------------------------------------------------------------------
// att logits: l[p] = b + sum_c w[c] * G[c][p]
// ---------------------------------------------------------------------------
__global__ void k_attlogit(const float* __restrict__ w, const float* __restrict__ b,
                           const float* __restrict__ G, float* __restrict__ L) {
    int p = blockIdx.x * blockDim.x + threadIdx.x;
    if (p >= P16_) return;
    float acc = b[0];
#pragma unroll 8
    for (int c = 0; c < CIN_; c++) acc += w[c] * G[(size_t)c * P16_ + p];
    L[p] = acc;
}

// softmax over j (rows of 4): row r in [0, 4096)
__global__ void k_softmax(const float* __restrict__ L, float* __restrict__ S) {
    int r = blockIdx.x * blockDim.x + threadIdx.x;
    if (r >= P4_) return;
    float l0 = L[r * 4 + 0], l1 = L[r * 4 + 1], l2 = L[r * 4 + 2], l3 = L[r * 4 + 3];
    float m = fmaxf(fmaxf(l0, l1), fmaxf(l2, l3));
    float e0 = expf(l0 - m), e1 = expf(l1 - m), e2 = expf(l2 - m), e3 = expf(l3 - m);
    float inv = 1.f / (e0 + e1 + e2 + e3);
    S[r * 4 + 0] = e0 * inv;
    S[r * 4 + 1] = e1 * inv;
    S[r * 4 + 2] = e2 * inv;
    S[r * 4 + 3] = e3 * inv;
}

// ---------------------------------------------------------------------------
// final fuse + output permute: out[bt*2176 + d*4 + i]
// ---------------------------------------------------------------------------
__global__ void k_fuse(const float* __restrict__ F, const float* __restrict__ FS,
                       const float* __restrict__ FT, const float* __restrict__ AG,
                       const float* __restrict__ S, float* __restrict__ out) {
    int idx = blockIdx.x * blockDim.x + threadIdx.x;
    if (idx >= BT_ * 2176) return;
    int bt = idx / 2176;
    int rem = idx % 2176;
    int d = rem >> 2, i = rem & 3;
    int ri = bt * 4 + i;
    float acc = F[(size_t)d * P4_ + ri];
#pragma unroll
    for (int j = 0; j < 4; j++) {
        float a = S[ri * 4 + j];
        if (j == i) {
            acc = fmaf(FS[(size_t)d * P4_ + ri], a, acc);
        } else {
            float tv = FT[(size_t)d * P4_ + bt * 4 + j];
            float ag = AG[(size_t)d * P16_ + bt * 16 + i * 4 + j];
            acc = fmaf(tv * ag, a, acc);
        }
    }
    out[idx] = acc;
}

// ---------------------------------------------------------------------------
extern "C" void kernel_launch(void* const* d_in, const int* in_sizes, int n_in,
                              void* d_out, int out_size) {
    const float* x      = (const float*)d_in[0];
    const float* pos2d  = (const float*)d_in[1];
    const float* w_pos  = (const float*)d_in[2];
    const float* b_pos  = (const float*)d_in[3];
    const float* w_e    = (const float*)d_in[4];
    const float* bn_e   = (const float*)d_in[5];
    const float* w1     = (const float*)d_in[6];
    const float* bn1    = (const float*)d_in[7];
    const float* w2     = (const float*)d_in[8];
    const float* bn2    = (const float*)d_in[9];
    const float* w_ag   = (const float*)d_in[10];
    const float* bn_ag  = (const float*)d_in[11];
    const float* w_ag_s = (const float*)d_in[12];
    const float* b_ag_s = (const float*)d_in[13];
    const float* w_att  = (const float*)d_in[14];
    const float* bn_att = (const float*)d_in[15];
    const float* w_att_s= (const float*)d_in[16];
    const float* b_att_s= (const float*)d_in[17];
    const float* Wsm    = (const float*)d_in[18];
    float* out = (float*)d_out;

    float* base = nullptr;
    cudaGetSymbolAddress((void**)&base, g_BUF);

    float* F    = base + OFF_F;
    float* P2   = base + OFF_P2;
    float* A    = base + OFF_A;
    float* Bv   = base + OFF_B;
    float* PP   = base + OFF_PP;
    float* H0   = base + OFF_H0;
    float* H1   = base + OFF_H1;
    float* H2   = base + OFF_H2;
    float* G    = base + OFF_G;
    float* AG   = base + OFF_AG;
    float* ATTL = base + OFF_ATTL;
    float* ATTS = base + OFF_ATTS;
    float* FS   = base + OFF_FS;
    float* FT   = base + OFF_FT;
    float* W0T  = base + OFF_W0T;
    float* W1T  = base + OFF_W1T;
    float* SBN  = base + OFF_SBN;

    // prep
    k_bn_fold<<<(5 * CIN_ + 255) / 256, 256>>>(bn_e, bn1, bn2, bn_ag, bn_att, SBN);
    k_wT<<<(2 * C_ * C_ + 255) / 256, 256>>>(Wsm, W0T, W1T);
    k_build_f<<<(C_ * P4_ + 255) / 256, 256>>>(x, F);
    k_build_p<<<(PCH_ * P4_ + 255) / 256, 256>>>(pos2d, P2);

    // layer 1 (separable): A = We[:, :C] @ f ; Bv = We[:, C:] @ f
    dim3 g1(P4_ / 128, (CIN_ + 127) / 128);
    sgemm<0><<<g1, 256>>>(w_e, CIN_, F, A, CIN_, P4_, C_, nullptr, nullptr, nullptr);
    sgemm<0><<<g1, 256>>>(w_e + C_, CIN_, F, Bv, CIN_, P4_, C_, nullptr, nullptr, nullptr);
    k_pos<<<(CIN_ * P4_ + 255) / 256, 256>>>(w_pos, P2, PP);
    k_h0<<<(CIN_ * P16_ + 255) / 256, 256>>>(A, Bv, PP, b_pos, SBN /*bn_expand*/, H0);

    // trunk
    dim3 g2(P16_ / 128, (CIN_ + 127) / 128);
    sgemm<1><<<g2, 256>>>(w1, CIN_, H0, H1, CIN_, P16_, CIN_,
                          SBN + 1 * 2 * CIN_, SBN + 1 * 2 * CIN_ + CIN_, nullptr);
    sgemm<2><<<g2, 256>>>(w2, CIN_, H1, H2, CIN_, P16_, CIN_,
                          SBN + 2 * 2 * CIN_, SBN + 2 * 2 * CIN_ + CIN_, H0);

    // aggregation branch
    sgemm<1><<<g2, 256>>>(w_ag, CIN_, H2, G, CIN_, P16_, CIN_,
                          SBN + 3 * 2 * CIN_, SBN + 3 * 2 * CIN_ + CIN_, nullptr);
    dim3 g3(P16_ / 128, (C_ + 127) / 128);
    sgemm<3><<<g3, 256>>>(w_ag_s, CIN_, G, AG, C_, P16_, CIN_, b_ag_s, nullptr, nullptr);

    // attention branch (reuse G)
    sgemm<1><<<g2, 256>>>(w_att, CIN_, H2, G, CIN_, P16_, CIN_,
                          SBN + 4 * 2 * CIN_, SBN + 4 * 2 * CIN_ + CIN_, nullptr);
    k_attlogit<<<(P16_ + 255) / 256, 256>>>(w_att_s, b_att_s, G, ATTL);
    k_softmax<<<(P4_ + 255) / 256, 256>>>(ATTL, ATTS);

    // self / transfer projections
    dim3 g4(P4_ / 128, (C_ + 127) / 128);
    sgemm<0><<<g4, 256>>>(W0T, C_, F, FS, C_, P4_, C_, nullptr, nullptr, nullptr);
    sgemm<0><<<g4, 256>>>(W1T, C_, F, FT, C_, P4_, C_, nullptr, nullptr, nullptr);

    // fuse + permute to output
    k_fuse<<<(BT_ * 2176 + 255) / 256, 256>>>(F, FS, FT, AG, ATTS, out);
}

// round 4
// speedup vs baseline: 1.5999x; 1.5967x over previous
#include <cuda_runtime.h>
#include <cuda_bf16.h>
#include <stdint.h>
#include <math.h>

namespace fv {
constexpr int C_ = 544, CIN_ = 1088, BT_ = 1024, P4_ = 4096, P16_ = 16384, PCH_ = 34;

// fp32 scratch (elements), all pixel-major rows
constexpr size_t OF_F    = 0;                             // [P4][544]
constexpr size_t OF_P2   = OF_F    + (size_t)P4_*C_;      // [P4][34]
constexpr size_t OF_WPT  = OF_P2   + (size_t)P4_*PCH_;    // [34][1088]
constexpr size_t OF_PP   = OF_WPT  + (size_t)PCH_*CIN_;   // [P4][1088]
constexpr size_t OF_A    = OF_PP   + (size_t)P4_*CIN_;
constexpr size_t OF_BV   = OF_A    + (size_t)P4_*CIN_;
constexpr size_t OF_H0F  = OF_BV   + (size_t)P4_*CIN_;    // [P16][1088]
constexpr size_t OF_GATT = OF_H0F  + (size_t)P16_*CIN_;   // [P16][1088]
constexpr size_t OF_AG   = OF_GATT + (size_t)P16_*CIN_;   // [P16][544]
constexpr size_t OF_FS   = OF_AG   + (size_t)P16_*C_;     // [P4][544]
constexpr size_t OF_FT   = OF_FS   + (size_t)P4_*C_;
constexpr size_t OF_ATTL = OF_FT   + (size_t)P4_*C_;
constexpr size_t OF_ATTS = OF_ATTL + (size_t)P16_;
constexpr size_t OF_SBN  = OF_ATTS + (size_t)P16_;        // [5][2][1088]
constexpr size_t TOT_F32 = OF_SBN + (size_t)5*2*CIN_;

// bf16 row-major scratch [rows][K]
constexpr size_t SZ_FB = (size_t)P4_ * C_;     // f: [4096][544]
constexpr size_t SZ_H  = (size_t)P16_ * CIN_;  // H*: [16384][1088]
constexpr size_t SZ_WE = (size_t)1152 * 544;
constexpr size_t SZ_WB = (size_t)1152 * 1088;
constexpr size_t SZ_WS = (size_t)640 * 1088;
constexpr size_t SZ_WT = (size_t)640 * 544;

constexpr size_t OB_FBH  = 0;
constexpr size_t OB_FBL  = OB_FBH  + SZ_FB;
constexpr size_t OB_H0H  = OB_FBL  + SZ_FB;
constexpr size_t OB_H0L  = OB_H0H  + SZ_H;
constexpr size_t OB_H1H  = OB_H0L  + SZ_H;
constexpr size_t OB_H1L  = OB_H1H  + SZ_H;
constexpr size_t OB_H2H  = OB_H1L  + SZ_H;
constexpr size_t OB_H2L  = OB_H2H  + SZ_H;
constexpr size_t OB_GH   = OB_H2L  + SZ_H;
constexpr size_t OB_GL   = OB_GH   + SZ_H;
constexpr size_t OB_WEAH = OB_GL   + SZ_H;
constexpr size_t OB_WEAL = OB_WEAH + SZ_WE;
constexpr size_t OB_WEBH = OB_WEAL + SZ_WE;
constexpr size_t OB_WEBL = OB_WEBH + SZ_WE;
constexpr size_t OB_W1H  = OB_WEBL + SZ_WE;
constexpr size_t OB_W1L  = OB_W1H  + SZ_WB;
constexpr size_t OB_W2H  = OB_W1L  + SZ_WB;
constexpr size_t OB_W2L  = OB_W2H  + SZ_WB;
constexpr size_t OB_WAGH = OB_W2L  + SZ_WB;
constexpr size_t OB_WAGL = OB_WAGH + SZ_WB;
constexpr size_t OB_WATH = OB_WAGL + SZ_WB;
constexpr size_t OB_WATL = OB_WATH + SZ_WB;
constexpr size_t OB_WSH  = OB_WATL + SZ_WB;
constexpr size_t OB_WSL  = OB_WSH  + SZ_WS;
constexpr size_t OB_W0TH = OB_WSL  + SZ_WS;
constexpr size_t OB_W0TL = OB_W0TH + SZ_WT;
constexpr size_t OB_W1TH = OB_W0TL + SZ_WT;
constexpr size_t OB_W1TL = OB_W1TH + SZ_WT;
constexpr size_t TOT_B16 = OB_W1TL + SZ_WT;
}  // namespace fv

__device__ float         g_F32[fv::TOT_F32];
__device__ __nv_bfloat16 g_B16[fv::TOT_B16];

using namespace fv;

// ---------------- baseline-PTX helpers (sm_80+, valid on sm_103) ----------------
__device__ __forceinline__ uint32_t smem_u32(const void* p) {
    uint32_t a;
    asm("{ .reg .u64 t; cvta.to.shared.u64 t, %1; cvt.u32.u64 %0, t; }" : "=r"(a) : "l"(p));
    return a;
}
__device__ __forceinline__ void cp16(uint32_t dst, const void* src) {
    asm volatile("cp.async.cg.shared.global [%0], [%1], 16;" :: "r"(dst), "l"(src));
}
#define CP_COMMIT() asm volatile("cp.async.commit_group;" ::: "memory")
#define CP_WAIT(n)  asm volatile("cp.async.wait_group %0;" :: "n"(n) : "memory")

__device__ __forceinline__ void ldsm_x4(uint32_t (&r)[4], uint32_t addr) {
    asm volatile("ldmatrix.sync.aligned.m8n8.x4.shared.b16 {%0,%1,%2,%3}, [%4];"
                 : "=r"(r[0]), "=r"(r[1]), "=r"(r[2]), "=r"(r[3]) : "r"(addr));
}
__device__ __forceinline__ void ldsm_x2(uint32_t (&r)[2], uint32_t addr) {
    asm volatile("ldmatrix.sync.aligned.m8n8.x2.shared.b16 {%0,%1}, [%2];"
                 : "=r"(r[0]), "=r"(r[1]) : "r"(addr));
}
__device__ __forceinline__ void mma_bf16(float (&d)[4], const uint32_t (&a)[4],
                                         const uint32_t (&b)[2]) {
    asm volatile(
        "mma.sync.aligned.m16n8k16.row.col.f32.bf16.bf16.f32 "
        "{%0,%1,%2,%3}, {%4,%5,%6,%7}, {%8,%9}, {%0,%1,%2,%3};"
        : "+f"(d[0]), "+f"(d[1]), "+f"(d[2]), "+f"(d[3])
        : "r"(a[0]), "r"(a[1]), "r"(a[2]), "r"(a[3]), "r"(b[0]), "r"(b[1]));
}
__device__ __forceinline__ void split_bf(float v, __nv_bfloat16& h, __nv_bfloat16& l) {
    h = __float2bfloat16(v);
    l = __float2bfloat16(v - __bfloat162float(h));
}

// ---------------- prep / elementwise ----------------
__global__ void k_bn_fold(const float* __restrict__ b0, const float* __restrict__ b1,
                          const float* __restrict__ b2, const float* __restrict__ b3,
                          const float* __restrict__ b4, float* __restrict__ sbn) {
    int idx = blockIdx.x * blockDim.x + threadIdx.x;
    if (idx >= 5 * CIN_) return;
    int w = idx / CIN_, c = idx % CIN_;
    const float* bn = w == 0 ? b0 : w == 1 ? b1 : w == 2 ? b2 : w == 3 ? b3 : b4;
    float s = bn[c] * rsqrtf(bn[3 * CIN_ + c] + 1e-5f);
    sbn[w * 2 * CIN_ + c] = s;
    sbn[w * 2 * CIN_ + CIN_ + c] = bn[CIN_ + c] - bn[2 * CIN_ + c] * s;
}

__global__ void k_wposT(const float* __restrict__ wpos, float* __restrict__ wpt) {
    int idx = blockIdx.x * blockDim.x + threadIdx.x;
    if (idx >= PCH_ * CIN_) return;
    int k = idx / CIN_, o = idx % CIN_;
    wpt[idx] = wpos[o * PCH_ + k];
}

// weight -> padded row-major [MP][K] bf16 hi/lo. trans: src[k*ld+r], else src[r*ld+k+koff]
__global__ void k_wprep(const float* __restrict__ src, int ld, int koff, int Msrc, int K,
                        int MP, int trans,
                        __nv_bfloat16* __restrict__ hi, __nv_bfloat16* __restrict__ lo) {
    int K8 = K >> 3;
    int idx = blockIdx.x * blockDim.x + threadIdx.x;
    if (idx >= MP * K8) return;
    int r = idx / K8, k0 = (idx % K8) * 8;
    union { __nv_bfloat16 h[8]; uint4 v; } ph, pl;
#pragma unroll
    for (int e = 0; e < 8; e++) {
        int k = k0 + e;
        float x = 0.f;
        if (r < Msrc) x = trans ? src[(size_t)k * ld + r] : src[(size_t)r * ld + k + koff];
        split_bf(x, ph.h[e], pl.h[e]);
    }
    size_t o = (size_t)r * K + k0;
    *reinterpret_cast<uint4*>(hi + o) = ph.v;
    *reinterpret_cast<uint4*>(lo + o) = pl.v;
}

__global__ void k_build_f(const float* __restrict__ x, float* __restrict__ F,
                          __nv_bfloat16* __restrict__ fh, __nv_bfloat16* __restrict__ fl) {
    int idx = blockIdx.x * blockDim.x + threadIdx.x;
    if (idx >= P4_ * 68) return;
    int p = idx / 68, c0 = (idx % 68) * 8;
    int bt = p >> 2, n = p & 3;
    union { __nv_bfloat16 h[8]; uint4 v; } ph, pl;
    float vv[8];
#pragma unroll
    for (int e = 0; e < 8; e++) {
        vv[e] = x[((size_t)bt * C_ + c0 + e) * 4 + n];
        split_bf(vv[e], ph.h[e], pl.h[e]);
    }
    size_t o = (size_t)p * C_ + c0;
    *reinterpret_cast<uint4*>(fh + o) = ph.v;
    *reinterpret_cast<uint4*>(fl + o) = pl.v;
    float4* d = reinterpret_cast<float4*>(F + o);
    d[0] = make_float4(vv[0], vv[1], vv[2], vv[3]);
    d[1] = make_float4(vv[4], vv[5], vv[6], vv[7]);
}

__global__ void k_build_p(const float* __restrict__ pos, float* __restrict__ P2) {
    int idx = blockIdx.x * blockDim.x + threadIdx.x;
    if (idx >= P4_ * PCH_) return;
    int p = idx / PCH_, k = idx % PCH_;
    P2[idx] = pos[((size_t)(p >> 2) * PCH_ + k) * 4 + (p & 3)];
}

__global__ void k_pos(const float* __restrict__ wpt, const float* __restrict__ P2,
                      float* __restrict__ PP) {
    int idx = blockIdx.x * blockDim.x + threadIdx.x;
    if (idx >= P4_ * CIN_) return;
    int p = idx / CIN_, o = idx % CIN_;
    float acc = 0.f;
#pragma unroll
    for (int k = 0; k < PCH_; k++) acc = fmaf(wpt[k * CIN_ + o], P2[p * PCH_ + k], acc);
    PP[idx] = acc;
}

__global__ void k_h0(const float* __restrict__ A, const float* __restrict__ Bv,
                     const float* __restrict__ PP, const float* __restrict__ bpos,
                     const float* __restrict__ sbn, float* __restrict__ H0f,
                     __nv_bfloat16* __restrict__ hh, __nv_bfloat16* __restrict__ hl) {
    int idx = blockIdx.x * blockDim.x + threadIdx.x;
    if (idx >= P16_ * 136) return;
    int p16 = idx / 136, o0 = (idx % 136) * 8;
    int bt = p16 >> 4, ij = p16 & 15, i = ij >> 2, j = ij & 3;
    size_t pi = (size_t)(bt * 4 + i) * CIN_ + o0;
    size_t pj = (size_t)(bt * 4 + j) * CIN_ + o0;
    union { __nv_bfloat16 h[8]; uint4 v; } ph, pl;
    float out[8];
#pragma unroll
    for (int e = 0; e < 8; e++) {
        int o = o0 + e;
        float v = fmaxf(fmaf(sbn[o], A[pi + e] + Bv[pj + e], sbn[CIN_ + o]), 0.f);
        out[e] = v + PP[pi + e] - PP[pj + e] + bpos[o];
        split_bf(out[e], ph.h[e], pl.h[e]);
    }
    size_t o = (size_t)p16 * CIN_ + o0;
    float4* d = reinterpret_cast<float4*>(H0f + o);
    d[0] = make_float4(out[0], out[1], out[2], out[3]);
    d[1] = make_float4(out[4], out[5], out[6], out[7]);
    *reinterpret_cast<uint4*>(hh + o) = ph.v;
    *reinterpret_cast<uint4*>(hl + o) = pl.v;
}

__global__ void k_attlogit(const float* __restrict__ w, const float* __restrict__ b,
                           const float* __restrict__ G, float* __restrict__ L) {
    int wid = threadIdx.x >> 5, lid = threadIdx.x & 31;
    int p = blockIdx.x * 8 + wid;
    if (p >= P16_) return;
    const float* row = G + (size_t)p * CIN_;
    float acc = 0.f;
#pragma unroll
    for (int c = lid; c < CIN_; c += 32) acc = fmaf(w[c], row[c], acc);
#pragma unroll
    for (int o = 16; o > 0; o >>= 1) acc += __shfl_xor_sync(0xFFFFFFFFu, acc, o);
    if (lid == 0) L[p] = acc + b[0];
}

__global__ void k_softmax(const float* __restrict__ L, float* __restrict__ S) {
    int r = blockIdx.x * blockDim.x + threadIdx.x;
    if (r >= P4_) return;
    float l0 = L[r*4], l1 = L[r*4+1], l2 = L[r*4+2], l3 = L[r*4+3];
    float m = fmaxf(fmaxf(l0, l1), fmaxf(l2, l3));
    float e0 = __expf(l0-m), e1 = __expf(l1-m), e2 = __expf(l2-m), e3 = __expf(l3-m);
    float inv = 1.f / (e0+e1+e2+e3);
    S[r*4]=e0*inv; S[r*4+1]=e1*inv; S[r*4+2]=e2*inv; S[r*4+3]=e3*inv;
}

__global__ void k_fuse(const float* __restrict__ F, const float* __restrict__ FS,
                       const float* __restrict__ FT, const float* __restrict__ AG,
                       const float* __restrict__ S, float* __restrict__ out) {
    int idx = blockIdx.x * blockDim.x + threadIdx.x;
    if (idx >= BT_ * 2176) return;
    int bt = idx / 2176, rem = idx % 2176;
    int i = rem / C_, d = rem % C_;
    int ri = bt * 4 + i;
    float acc = F[(size_t)ri * C_ + d];
#pragma unroll
    for (int j = 0; j < 4; j++) {
        float a = S[ri * 4 + j];
        if (j == i) acc = fmaf(FS[(size_t)ri * C_ + d], a, acc);
        else acc = fmaf(FT[(size_t)(bt*4+j) * C_ + d] * AG[(size_t)(bt*16+i*4+j) * C_ + d], a, acc);
    }
    out[(size_t)bt * 2176 + d * 4 + i] = acc;
}

// ---------------- HMMA split-bf16 GEMM ----------------
// C[m=outch][n=pixel] = W[MP][K] @ X[NP][K]^T, 3-pass split accumulate.
// EPI: 0 fp32 | 1 relu(s*v+t) fp32 | 2 relu->bf16 h/l | 3 resid+relu->bf16 | 4 v+bias fp32
constexpr int BKP    = 40;              // padded smem row (elems) -> conflict-free ldmatrix
constexpr int TILE_B = 128 * BKP * 2;   // 10240 B per operand tile
constexpr int STG_B  = 4 * TILE_B;      // Ah|Al|Bh|Bl
constexpr int SMEMB  = 2 * STG_B;       // 81920 B (Cs 128x132 f32 = 67584 aliases here)

template <int EPI>
__global__ void __launch_bounds__(256, 1)
gemm_mma(const __nv_bfloat16* __restrict__ Ahg, const __nv_bfloat16* __restrict__ Alg,
         const __nv_bfloat16* __restrict__ Bhg, const __nv_bfloat16* __restrict__ Blg,
         int K, int KB, int Mreal,
         float* __restrict__ outf, int ldo,
         __nv_bfloat16* __restrict__ ohi, __nv_bfloat16* __restrict__ olo, int ldob,
         const float* __restrict__ sv, const float* __restrict__ tv,
         const float* __restrict__ resid) {
    extern __shared__ __nv_bfloat16 smbuf[];
    const uint32_t sb = smem_u32(smbuf);
    const int tid = threadIdx.x, lane = tid & 31, wid = tid >> 5;
    const int mt = blockIdx.x, nt = blockIdx.y;
    const int wm = (wid >> 2) * 64, wn = (wid & 3) * 32;

    float acc[4][4][4];
#pragma unroll
    for (int a = 0; a < 4; a++)
#pragma unroll
        for (int b = 0; b < 4; b++)
#pragma unroll
            for (int c = 0; c < 4; c++) acc[a][b][c] = 0.f;

    auto load_stage = [&](int s, int kb) {
        uint32_t dstb = sb + s * STG_B;
        int k0 = kb * 32;
#pragma unroll
        for (int c = 0; c < 2; c++) {
            int q = tid + c * 256;
            int r = q >> 2, kc = (q & 3) * 8;
            uint32_t d = dstb + (r * BKP + kc) * 2;
            size_t offA = (size_t)(mt * 128 + r) * K + k0 + kc;
            size_t offB = (size_t)(nt * 128 + r) * K + k0 + kc;
            cp16(d,              Ahg + offA);
            cp16(d + TILE_B,     Alg + offA);
            cp16(d + 2 * TILE_B, Bhg + offB);
            cp16(d + 3 * TILE_B, Blg + offB);
        }
    };

    auto compute_stage = [&](int s) {
        uint32_t base = sb + s * STG_B;
        int grp = lane >> 3, lrow = lane & 7;
        int l16 = lane & 15, selB = l16 >> 3, lrB = l16 & 7;
#pragma unroll
        for (int ks = 0; ks < 32; ks += 16) {
            uint32_t ah[4][4], al[4][4], bh[4][2], bl[4][2];
#pragma unroll
            for (int mi = 0; mi < 4; mi++) {
                int row = wm + mi * 16 + (grp & 1) * 8 + lrow;
                int col = ks + (grp >> 1) * 8;
                uint32_t a = base + (row * BKP + col) * 2;
                ldsm_x4(ah[mi], a);
                ldsm_x4(al[mi], a + TILE_B);
            }
#pragma unroll
            for (int ni = 0; ni < 4; ni++) {
                int row = wn + ni * 8 + lrB;
                int col = ks + selB * 8;
                uint32_t a = base + 2 * TILE_B + (row * BKP + col) * 2;
                ldsm_x2(bh[ni], a);
                ldsm_x2(bl[ni], a + TILE_B);
            }
#pragma unroll
            for (int mi = 0; mi < 4; mi++)
#pragma unroll
                for (int ni = 0; ni < 4; ni++) {
                    mma_bf16(acc[mi][ni], ah[mi], bh[ni]);
                    mma_bf16(acc[mi][ni], ah[mi], bl[ni]);
                    mma_bf16(acc[mi][ni], al[mi], bh[ni]);
                }
        }
    };

    load_stage(0, 0);
    CP_COMMIT();
    for (int kb = 0; kb < KB; kb++) {
        if (kb + 1 < KB) {
            load_stage((kb + 1) & 1, kb + 1);
            CP_COMMIT();
            CP_WAIT(1);
        } else {
            CP_WAIT(0);
        }
        __syncthreads();
        compute_stage(kb & 1);
        __syncthreads();
    }

    // transpose through smem -> coalesced [pixel][channel] stores
    float* Cs = reinterpret_cast<float*>(smbuf);
#pragma unroll
    for (int mi = 0; mi < 4; mi++)
#pragma unroll
        for (int ni = 0; ni < 4; ni++) {
            int rm = wm + mi * 16 + (lane >> 2);
            int cn = wn + ni * 8 + 2 * (lane & 3);
            Cs[cn * 132 + rm]           = acc[mi][ni][0];
            Cs[(cn + 1) * 132 + rm]     = acc[mi][ni][1];
            Cs[cn * 132 + rm + 8]       = acc[mi][ni][2];
            Cs[(cn + 1) * 132 + rm + 8] = acc[mi][ni][3];
        }
    __syncthreads();

    {
        int nl = tid >> 1, m0 = (tid & 1) * 64;
        int ng = nt * 128 + nl;
        int mg0 = mt * 128 + m0;
#pragma unroll 4
        for (int j = 0; j < 64; j++) {
            int m = mg0 + j;
            if (m >= Mreal) break;
            float v = Cs[nl * 132 + m0 + j];
            if constexpr (EPI == 0) {
                outf[(size_t)ng * ldo + m] = v;
            } else if constexpr (EPI == 1) {
                outf[(size_t)ng * ldo + m] = fmaxf(fmaf(sv[m], v, tv[m]), 0.f);
            } else if constexpr (EPI == 4) {
                outf[(size_t)ng * ldo + m] = v + sv[m];
            } else {
                float w = fmaxf(fmaf(sv[m], v, tv[m]), 0.f);
                if constexpr (EPI == 3) w += resid[(size_t)ng * ldob + m];
                __nv_bfloat16 h, l;
                split_bf(w, h, l);
                ohi[(size_t)ng * ldob + m] = h;
                olo[(size_t)ng * ldob + m] = l;
            }
        }
    }
}

// ---------------- launch ----------------
extern "C" void kernel_launch(void* const* d_in, const int* in_sizes, int n_in,
                              void* d_out, int out_size) {
    const float *x = (const float*)d_in[0], *pos2d = (const float*)d_in[1];
    const float *w_pos = (const float*)d_in[2], *b_pos = (const float*)d_in[3];
    const float *w_e = (const float*)d_in[4],  *w1 = (const float*)d_in[6];
    const float *w2 = (const float*)d_in[8],   *w_ag = (const float*)d_in[10];
    const float *w_ag_s = (const float*)d_in[12], *b_ag_s = (const float*)d_in[13];
    const float *w_att = (const float*)d_in[14], *w_att_s = (const float*)d_in[16];
    const float *b_att_s = (const float*)d_in[17], *Wsm = (const float*)d_in[18];
    float* out = (float*)d_out;

    float* F32 = nullptr;  __nv_bfloat16* B16 = nullptr;
    cudaGetSymbolAddress((void**)&F32, g_F32);
    cudaGetSymbolAddress((void**)&B16, g_B16);

    float *F = F32+OF_F, *P2 = F32+OF_P2, *WPT = F32+OF_WPT, *PP = F32+OF_PP;
    float *A = F32+OF_A, *BV = F32+OF_BV, *H0F = F32+OF_H0F, *GATT = F32+OF_GATT;
    float *AG = F32+OF_AG, *FS = F32+OF_FS, *FT = F32+OF_FT;
    float *ATTL = F32+OF_ATTL, *ATTS = F32+OF_ATTS, *SBN = F32+OF_SBN;

    cudaFuncSetAttribute(gemm_mma<0>, cudaFuncAttributeMaxDynamicSharedMemorySize, SMEMB);
    cudaFuncSetAttribute(gemm_mma<1>, cudaFuncAttributeMaxDynamicSharedMemorySize, SMEMB);
    cudaFuncSetAttribute(gemm_mma<2>, cudaFuncAttributeMaxDynamicSharedMemorySize, SMEMB);
    cudaFuncSetAttribute(gemm_mma<3>, cudaFuncAttributeMaxDynamicSharedMemorySize, SMEMB);
    cudaFuncSetAttribute(gemm_mma<4>, cudaFuncAttributeMaxDynamicSharedMemorySize, SMEMB);

    k_bn_fold<<<(5*CIN_+255)/256, 256>>>((const float*)d_in[5], (const float*)d_in[7],
                                         (const float*)d_in[9], (const float*)d_in[11],
                                         (const float*)d_in[15], SBN);
    k_wposT<<<(PCH_*CIN_+255)/256, 256>>>(w_pos, WPT);
    k_build_f<<<(P4_*68+255)/256, 256>>>(x, F, B16+OB_FBH, B16+OB_FBL);
    k_build_p<<<(P4_*PCH_+255)/256, 256>>>(pos2d, P2);
    k_pos<<<(P4_*CIN_+255)/256, 256>>>(WPT, P2, PP);

    // weights -> padded row-major bf16 hi/lo
    k_wprep<<<(1152*68+255)/256,256>>>(w_e, CIN_, 0,   1088, 544,  1152, 0, B16+OB_WEAH, B16+OB_WEAL);
    k_wprep<<<(1152*68+255)/256,256>>>(w_e, CIN_, 544, 1088, 544,  1152, 0, B16+OB_WEBH, B16+OB_WEBL);
    k_wprep<<<(1152*136+255)/256,256>>>(w1,   CIN_, 0, 1088, 1088, 1152, 0, B16+OB_W1H,  B16+OB_W1L);
    k_wprep<<<(1152*136+255)/256,256>>>(w2,   CIN_, 0, 1088, 1088, 1152, 0, B16+OB_W2H,  B16+OB_W2L);
    k_wprep<<<(1152*136+255)/256,256>>>(w_ag, CIN_, 0, 1088, 1088, 1152, 0, B16+OB_WAGH, B16+OB_WAGL);
    k_wprep<<<(1152*136+255)/256,256>>>(w_att,CIN_, 0, 1088, 1088, 1152, 0, B16+OB_WATH, B16+OB_WATL);
    k_wprep<<<(640*136+255)/256,256>>>(w_ag_s, CIN_, 0, 544, 1088, 640, 0, B16+OB_WSH, B16+OB_WSL);
    k_wprep<<<(640*68+255)/256,256>>>(Wsm,            C_, 0, 544, 544, 640, 1, B16+OB_W0TH, B16+OB_W0TL);
    k_wprep<<<(640*68+255)/256,256>>>(Wsm + C_*C_,    C_, 0, 544, 544, 640, 1, B16+OB_W1TH, B16+OB_W1TL);

    // layer 1 (separable halves): A = We[:, :C]@f ; BV = We[:, C:]@f
    gemm_mma<0><<<dim3(9,32),256,SMEMB>>>(B16+OB_WEAH,B16+OB_WEAL, B16+OB_FBH,B16+OB_FBL,
                                          544, 17, 1088, A, CIN_, nullptr,nullptr,0,
                                          nullptr,nullptr,nullptr);
    gemm_mma<0><<<dim3(9,32),256,SMEMB>>>(B16+OB_WEBH,B16+OB_WEBL, B16+OB_FBH,B16+OB_FBL,
                                          544, 17, 1088, BV, CIN_, nullptr,nullptr,0,
                                          nullptr,nullptr,nullptr);
    k_h0<<<(P16_*136+255)/256, 256>>>(A, BV, PP, b_pos, SBN, H0F, B16+OB_H0H, B16+OB_H0L);

    // trunk
    gemm_mma<2><<<dim3(9,128),256,SMEMB>>>(B16+OB_W1H,B16+OB_W1L, B16+OB_H0H,B16+OB_H0L,
                                           1088, 34, 1088, nullptr,0, B16+OB_H1H,B16+OB_H1L,CIN_,
                                           SBN+2*CIN_, SBN+3*CIN_, nullptr);
    gemm_mma<3><<<dim3(9,128),256,SMEMB>>>(B16+OB_W2H,B16+OB_W2L, B16+OB_H1H,B16+OB_H1L,
                                           1088, 34, 1088, nullptr,0, B16+OB_H2H,B16+OB_H2L,CIN_,
                                           SBN+4*CIN_, SBN+5*CIN_, H0F);
    // aggregation branch
    gemm_mma<2><<<dim3(9,128),256,SMEMB>>>(B16+OB_WAGH,B16+OB_WAGL, B16+OB_H2H,B16+OB_H2L,
                                           1088, 34, 1088, nullptr,0, B16+OB_GH,B16+OB_GL,CIN_,
                                           SBN+6*CIN_, SBN+7*CIN_, nullptr);
    gemm_mma<4><<<dim3(5,128),256,SMEMB>>>(B16+OB_WSH,B16+OB_WSL, B16+OB_GH,B16+OB_GL,
                                           1088, 34, 544, AG, C_, nullptr,nullptr,0,
                                           b_ag_s, nullptr, nullptr);
    // attention branch
    gemm_mma<1><<<dim3(9,128),256,SMEMB>>>(B16+OB_WATH,B16+OB_WATL, B16+OB_H2H,B16+OB_H2L,
                                           1088, 34, 1088, GATT, CIN_, nullptr,nullptr,0,
                                           SBN+8*CIN_, SBN+9*CIN_, nullptr);
    k_attlogit<<<P16_/8, 256>>>(w_att_s, b_att_s, GATT, ATTL);
    k_softmax<<<(P4_+255)/256, 256>>>(ATTL, ATTS);

    // self / transfer projections
    gemm_mma<0><<<dim3(5,32),256,SMEMB>>>(B16+OB_W0TH,B16+OB_W0TL, B16+OB_FBH,B16+OB_FBL,
                                          544, 17, 544, FS, C_, nullptr,nullptr,0,
                                          nullptr,nullptr,nullptr);
    gemm_mma<0><<<dim3(5,32),256,SMEMB>>>(B16+OB_W1TH,B16+OB_W1TL, B16+OB_FBH,B16+OB_FBL,
                                          544, 17, 544, FT, C_, nullptr,nullptr,0,
                                          nullptr,nullptr,nullptr);

    k_fuse<<<(BT_*2176+255)/256, 256>>>(F, FS, FT, AG, ATTS, out);
}

// round 5
// speedup vs baseline: 3.0084x; 1.8804x over previous
#include <cuda_runtime.h>
#include <cuda_bf16.h>
#include <stdint.h>
#include <math.h>

namespace fv {
constexpr int C_ = 544, CIN_ = 1088, BT_ = 1024, P4_ = 4096, P16_ = 16384, PCH_ = 34;

// fp32 scratch (elements)
constexpr size_t OF_F    = 0;                              // [P4][544]
constexpr size_t OF_P2   = OF_F    + (size_t)P4_*C_;       // [P4][34]
constexpr size_t OF_WPT  = OF_P2   + (size_t)P4_*PCH_;     // [34][1088]
constexpr size_t OF_PP   = OF_WPT  + (size_t)PCH_*CIN_;    // [P4][1088]
constexpr size_t OF_AB   = OF_PP   + (size_t)P4_*CIN_;     // [P4][2176] (A | BV)
constexpr size_t OF_H0F  = OF_AB   + (size_t)P4_*2176;     // [P16][1088]
constexpr size_t OF_AG   = OF_H0F  + (size_t)P16_*CIN_;    // [P16][544]
constexpr size_t OF_FST  = OF_AG   + (size_t)P16_*C_;      // [P4][1088] (FS | FT)
constexpr size_t OF_ATTL = OF_FST  + (size_t)P4_*CIN_;
constexpr size_t OF_ATTS = OF_ATTL + (size_t)P16_;
constexpr size_t OF_SBN  = OF_ATTS + (size_t)P16_;         // [5][2][1088]
constexpr size_t TOT_F32 = OF_SBN + (size_t)5*2*CIN_;

// bf16 row-major scratch [rows][K]
constexpr size_t SZ_FB  = (size_t)P4_ * C_;
constexpr size_t SZ_H   = (size_t)P16_ * CIN_;
constexpr size_t SZ_WE  = (size_t)2176 * 544;   // stacked We halves
constexpr size_t SZ_WB  = (size_t)1152 * 1088;
constexpr size_t SZ_WS  = (size_t)640 * 1088;
constexpr size_t SZ_W01 = (size_t)1152 * 544;   // stacked W0T/W1T

constexpr size_t OB_FBH  = 0;
constexpr size_t OB_FBL  = OB_FBH  + SZ_FB;
constexpr size_t OB_H0H  = OB_FBL  + SZ_FB;
constexpr size_t OB_H0L  = OB_H0H  + SZ_H;
constexpr size_t OB_H1H  = OB_H0L  + SZ_H;
constexpr size_t OB_H1L  = OB_H1H  + SZ_H;
constexpr size_t OB_H2H  = OB_H1L  + SZ_H;
constexpr size_t OB_H2L  = OB_H2H  + SZ_H;
constexpr size_t OB_GH   = OB_H2L  + SZ_H;
constexpr size_t OB_GL   = OB_GH   + SZ_H;
constexpr size_t OB_WEH  = OB_GL   + SZ_H;
constexpr size_t OB_WEL  = OB_WEH  + SZ_WE;
constexpr size_t OB_W1H  = OB_WEL  + SZ_WE;
constexpr size_t OB_W1L  = OB_W1H  + SZ_WB;
constexpr size_t OB_W2H  = OB_W1L  + SZ_WB;
constexpr size_t OB_W2L  = OB_W2H  + SZ_WB;
constexpr size_t OB_WAGH = OB_W2L  + SZ_WB;
constexpr size_t OB_WAGL = OB_WAGH + SZ_WB;
constexpr size_t OB_WATH = OB_WAGL + SZ_WB;
constexpr size_t OB_WATL = OB_WATH + SZ_WB;
constexpr size_t OB_WSH  = OB_WATL + SZ_WB;
constexpr size_t OB_WSL  = OB_WSH  + SZ_WS;
constexpr size_t OB_W01H = OB_WSL  + SZ_WS;
constexpr size_t OB_W01L = OB_W01H + SZ_W01;
constexpr size_t TOT_B16 = OB_W01L + SZ_W01;
}  // namespace fv

__device__ float         g_F32[fv::TOT_F32];
__device__ __nv_bfloat16 g_B16[fv::TOT_B16];

using namespace fv;

// ---------------- baseline-PTX helpers ----------------
__device__ __forceinline__ uint32_t smem_u32(const void* p) {
    uint32_t a;
    asm("{ .reg .u64 t; cvta.to.shared.u64 t, %1; cvt.u32.u64 %0, t; }" : "=r"(a) : "l"(p));
    return a;
}
__device__ __forceinline__ void cp16(uint32_t dst, const void* src) {
    asm volatile("cp.async.cg.shared.global [%0], [%1], 16;" :: "r"(dst), "l"(src));
}
#define CP_COMMIT() asm volatile("cp.async.commit_group;" ::: "memory")
#define CP_WAIT(n)  asm volatile("cp.async.wait_group %0;" :: "n"(n) : "memory")

__device__ __forceinline__ void ldsm_x4(uint32_t (&r)[4], uint32_t addr) {
    asm volatile("ldmatrix.sync.aligned.m8n8.x4.shared.b16 {%0,%1,%2,%3}, [%4];"
                 : "=r"(r[0]), "=r"(r[1]), "=r"(r[2]), "=r"(r[3]) : "r"(addr));
}
__device__ __forceinline__ void ldsm_x2(uint32_t (&r)[2], uint32_t addr) {
    asm volatile("ldmatrix.sync.aligned.m8n8.x2.shared.b16 {%0,%1}, [%2];"
                 : "=r"(r[0]), "=r"(r[1]) : "r"(addr));
}
__device__ __forceinline__ void mma_bf16(float (&d)[4], const uint32_t (&a)[4],
                                         const uint32_t (&b)[2]) {
    asm volatile(
        "mma.sync.aligned.m16n8k16.row.col.f32.bf16.bf16.f32 "
        "{%0,%1,%2,%3}, {%4,%5,%6,%7}, {%8,%9}, {%0,%1,%2,%3};"
        : "+f"(d[0]), "+f"(d[1]), "+f"(d[2]), "+f"(d[3])
        : "r"(a[0]), "r"(a[1]), "r"(a[2]), "r"(a[3]), "r"(b[0]), "r"(b[1]));
}
__device__ __forceinline__ void split_bf(float v, __nv_bfloat16& h, __nv_bfloat16& l) {
    h = __float2bfloat16(v);
    l = __float2bfloat16(v - __bfloat162float(h));
}

// ---------------- prep / elementwise ----------------
__global__ void k_bn_fold(const float* __restrict__ b0, const float* __restrict__ b1,
                          const float* __restrict__ b2, const float* __restrict__ b3,
                          const float* __restrict__ b4, float* __restrict__ sbn) {
    int idx = blockIdx.x * blockDim.x + threadIdx.x;
    if (idx >= 5 * CIN_) return;
    int w = idx / CIN_, c = idx % CIN_;
    const float* bn = w == 0 ? b0 : w == 1 ? b1 : w == 2 ? b2 : w == 3 ? b3 : b4;
    float s = bn[c] * rsqrtf(bn[3 * CIN_ + c] + 1e-5f);
    sbn[w * 2 * CIN_ + c] = s;
    sbn[w * 2 * CIN_ + CIN_ + c] = bn[CIN_ + c] - bn[2 * CIN_ + c] * s;
}

__global__ void k_wposT(const float* __restrict__ wpos, float* __restrict__ wpt) {
    int idx = blockIdx.x * blockDim.x + threadIdx.x;
    if (idx >= PCH_ * CIN_) return;
    int k = idx / CIN_, o = idx % CIN_;
    wpt[idx] = wpos[o * PCH_ + k];
}

// weight -> padded row-major [MP][K] bf16 hi/lo.
// mode 0: src[r*ld + k]   (r < Msrc else 0)
// mode 2: stacked Wsm^T: src[(r/544)*295936 + k*544 + (r%544)]  (r < 1088)
// mode 3: stacked We:    src[(r%1088)*1088 + (r/1088)*544 + k]
__global__ void k_wprep(const float* __restrict__ src, int ld, int Msrc, int K,
                        int MP, int mode,
                        __nv_bfloat16* __restrict__ hi, __nv_bfloat16* __restrict__ lo) {
    int K8 = K >> 3;
    int idx = blockIdx.x * blockDim.x + threadIdx.x;
    if (idx >= MP * K8) return;
    int r = idx / K8, k0 = (idx % K8) * 8;
    union { __nv_bfloat16 h[8]; uint4 v; } ph, pl;
#pragma unroll
    for (int e = 0; e < 8; e++) {
        int k = k0 + e;
        float x = 0.f;
        if (r < Msrc) {
            if (mode == 0)      x = src[(size_t)r * ld + k];
            else if (mode == 2) x = src[(size_t)(r / 544) * 295936 + (size_t)k * 544 + (r % 544)];
            else                x = src[(size_t)(r % 1088) * 1088 + (size_t)(r / 1088) * 544 + k];
        }
        split_bf(x, ph.h[e], pl.h[e]);
    }
    size_t o = (size_t)r * K + k0;
    *reinterpret_cast<uint4*>(hi + o) = ph.v;
    *reinterpret_cast<uint4*>(lo + o) = pl.v;
}

__global__ void k_build_f(const float* __restrict__ x, float* __restrict__ F,
                          __nv_bfloat16* __restrict__ fh, __nv_bfloat16* __restrict__ fl) {
    int idx = blockIdx.x * blockDim.x + threadIdx.x;
    if (idx >= P4_ * 68) return;
    int p = idx / 68, c0 = (idx % 68) * 8;
    int bt = p >> 2, n = p & 3;
    union { __nv_bfloat16 h[8]; uint4 v; } ph, pl;
    float vv[8];
#pragma unroll
    for (int e = 0; e < 8; e++) {
        vv[e] = x[((size_t)bt * C_ + c0 + e) * 4 + n];
        split_bf(vv[e], ph.h[e], pl.h[e]);
    }
    size_t o = (size_t)p * C_ + c0;
    *reinterpret_cast<uint4*>(fh + o) = ph.v;
    *reinterpret_cast<uint4*>(fl + o) = pl.v;
    float4* d = reinterpret_cast<float4*>(F + o);
    d[0] = make_float4(vv[0], vv[1], vv[2], vv[3]);
    d[1] = make_float4(vv[4], vv[5], vv[6], vv[7]);
}

__global__ void k_build_p(const float* __restrict__ pos, float* __restrict__ P2) {
    int idx = blockIdx.x * blockDim.x + threadIdx.x;
    if (idx >= P4_ * PCH_) return;
    int p = idx / PCH_, k = idx % PCH_;
    P2[idx] = pos[((size_t)(p >> 2) * PCH_ + k) * 4 + (p & 3)];
}

__global__ void k_pos(const float* __restrict__ wpt, const float* __restrict__ P2,
                      float* __restrict__ PP) {
    int idx = blockIdx.x * blockDim.x + threadIdx.x;
    if (idx >= P4_ * CIN_) return;
    int p = idx / CIN_, o = idx % CIN_;
    float acc = 0.f;
#pragma unroll
    for (int k = 0; k < PCH_; k++) acc = fmaf(wpt[k * CIN_ + o], P2[p * PCH_ + k], acc);
    PP[idx] = acc;
}

__global__ void k_h0(const float* __restrict__ AB, const float* __restrict__ PP,
                     const float* __restrict__ bpos, const float* __restrict__ sbn,
                     float* __restrict__ H0f,
                     __nv_bfloat16* __restrict__ hh, __nv_bfloat16* __restrict__ hl) {
    int idx = blockIdx.x * blockDim.x + threadIdx.x;
    if (idx >= P16_ * 136) return;
    int p16 = idx / 136, o0 = (idx % 136) * 8;
    int bt = p16 >> 4, ij = p16 & 15, i = ij >> 2, j = ij & 3;
    size_t pa = (size_t)(bt * 4 + i) * 2176 + o0;
    size_t pb = (size_t)(bt * 4 + j) * 2176 + 1088 + o0;
    size_t qi = (size_t)(bt * 4 + i) * CIN_ + o0;
    size_t qj = (size_t)(bt * 4 + j) * CIN_ + o0;
    union { __nv_bfloat16 h[8]; uint4 v; } ph, pl;
    float out[8];
#pragma unroll
    for (int e = 0; e < 8; e++) {
        int o = o0 + e;
        float v = fmaxf(fmaf(sbn[o], AB[pa + e] + AB[pb + e], sbn[CIN_ + o]), 0.f);
        out[e] = v + PP[qi + e] - PP[qj + e] + bpos[o];
        split_bf(out[e], ph.h[e], pl.h[e]);
    }
    size_t o = (size_t)p16 * CIN_ + o0;
    float4* d = reinterpret_cast<float4*>(H0f + o);
    d[0] = make_float4(out[0], out[1], out[2], out[3]);
    d[1] = make_float4(out[4], out[5], out[6], out[7]);
    *reinterpret_cast<uint4*>(hh + o) = ph.v;
    *reinterpret_cast<uint4*>(hl + o) = pl.v;
}

// att logits from bf16 hi/lo G
__global__ void k_attlogit(const float* __restrict__ w, const float* __restrict__ b,
                           const __nv_bfloat16* __restrict__ gh,
                           const __nv_bfloat16* __restrict__ gl, float* __restrict__ L) {
    int wid = threadIdx.x >> 5, lid = threadIdx.x & 31;
    int p = blockIdx.x * 8 + wid;
    if (p >= P16_) return;
    const __nv_bfloat162* rh = reinterpret_cast<const __nv_bfloat162*>(gh + (size_t)p * CIN_);
    const __nv_bfloat162* rl = reinterpret_cast<const __nv_bfloat162*>(gl + (size_t)p * CIN_);
    float acc = 0.f;
#pragma unroll
    for (int it = 0; it < 17; it++) {
        int c2 = lid + it * 32;
        __nv_bfloat162 h = rh[c2], l = rl[c2];
        float2 hf = __bfloat1622float2(h), lf = __bfloat1622float2(l);
        acc = fmaf(w[c2 * 2], hf.x + lf.x, acc);
        acc = fmaf(w[c2 * 2 + 1], hf.y + lf.y, acc);
    }
#pragma unroll
    for (int o = 16; o > 0; o >>= 1) acc += __shfl_xor_sync(0xFFFFFFFFu, acc, o);
    if (lid == 0) L[p] = acc + b[0];
}

__global__ void k_softmax(const float* __restrict__ L, float* __restrict__ S) {
    int r = blockIdx.x * blockDim.x + threadIdx.x;
    if (r >= P4_) return;
    float l0 = L[r*4], l1 = L[r*4+1], l2 = L[r*4+2], l3 = L[r*4+3];
    float m = fmaxf(fmaxf(l0, l1), fmaxf(l2, l3));
    float e0 = __expf(l0-m), e1 = __expf(l1-m), e2 = __expf(l2-m), e3 = __expf(l3-m);
    float inv = 1.f / (e0+e1+e2+e3);
    S[r*4]=e0*inv; S[r*4+1]=e1*inv; S[r*4+2]=e2*inv; S[r*4+3]=e3*inv;
}

__global__ void k_fuse(const float* __restrict__ F, const float* __restrict__ FST,
                       const float* __restrict__ AG, const float* __restrict__ S,
                       float* __restrict__ out) {
    int idx = blockIdx.x * blockDim.x + threadIdx.x;
    if (idx >= BT_ * 2176) return;
    int bt = idx / 2176, rem = idx % 2176;
    int i = rem / C_, d = rem % C_;
    int ri = bt * 4 + i;
    float acc = F[(size_t)ri * C_ + d];
#pragma unroll
    for (int j = 0; j < 4; j++) {
        float a = S[ri * 4 + j];
        if (j == i) acc = fmaf(FST[(size_t)ri * CIN_ + d], a, acc);
        else acc = fmaf(FST[(size_t)(bt*4+j) * CIN_ + 544 + d] *
                        AG[(size_t)(bt*16+i*4+j) * C_ + d], a, acc);
    }
    out[(size_t)bt * 2176 + d * 4 + i] = acc;
}

// ---------------- HMMA split-bf16 GEMM (swizzled, 3-stage, 1 sync/stage) ----------------
// C[m=outch][n=pixel] = W[MP][K] @ X[NP][K]^T. 3 passes: AhBh + AhBl + AlBh.
// EPI: 0 fp32 | 1 relu fp32 | 2 relu->bf16 h/l | 3 resid+relu->bf16 | 4 v+bias fp32
constexpr int TIL = 8192;        // 128 rows x 64B
constexpr int STG = 4 * TIL;     // Ah|Al|Bh|Bl = 32 KB
constexpr int SMEMB = 3 * STG;   // 96 KB (Cs 128x132 f32 = 67.6 KB aliases)

__device__ __forceinline__ uint32_t swadr(uint32_t base, int row, int c16) {
    return base + row * 64 + ((c16 ^ ((row >> 1) & 3)) << 4);
}

template <int EPI>
__global__ void __launch_bounds__(256, 2)
gemm_mma(const __nv_bfloat16* __restrict__ Ahg, const __nv_bfloat16* __restrict__ Alg,
         const __nv_bfloat16* __restrict__ Bhg, const __nv_bfloat16* __restrict__ Blg,
         int K, int KB, int Mreal,
         float* __restrict__ outf, int ldo,
         __nv_bfloat16* __restrict__ ohi, __nv_bfloat16* __restrict__ olo, int ldob,
         const float* __restrict__ sv, const float* __restrict__ tv,
         const float* __restrict__ resid) {
    extern __shared__ __nv_bfloat16 smbuf[];
    const uint32_t sb = smem_u32(smbuf);
    const int tid = threadIdx.x, lane = tid & 31, wid = tid >> 5;
    const int mt = blockIdx.x, nt = blockIdx.y;
    const int wm = (wid >> 2) * 64, wn = (wid & 3) * 32;

    float acc[4][4][4];
#pragma unroll
    for (int a = 0; a < 4; a++)
#pragma unroll
        for (int b = 0; b < 4; b++)
#pragma unroll
            for (int c = 0; c < 4; c++) acc[a][b][c] = 0.f;

    auto load_stage = [&](int s, int kb) {
        uint32_t dstb = sb + s * STG;
        int k0 = kb * 32;
#pragma unroll
        for (int c = 0; c < 2; c++) {
            int q = tid + c * 256;
            int r = q >> 2, ch = q & 3;
            uint32_t d = dstb + r * 64 + ((ch ^ ((r >> 1) & 3)) << 4);
            size_t offA = (size_t)(mt * 128 + r) * K + k0 + ch * 8;
            size_t offB = (size_t)(nt * 128 + r) * K + k0 + ch * 8;
            cp16(d,           Ahg + offA);
            cp16(d + TIL,     Alg + offA);
            cp16(d + 2 * TIL, Bhg + offB);
            cp16(d + 3 * TIL, Blg + offB);
        }
    };

    const int grp = lane >> 3, lrow = lane & 7;
    const int l16 = lane & 15, selB = l16 >> 3, lrB = l16 & 7;

    auto compute_stage = [&](int s) {
        uint32_t base = sb + s * STG;
#pragma unroll
        for (int ks2 = 0; ks2 < 2; ks2++) {
            uint32_t af[4][4], bf[4][2], bl2[4][2];
            int cA = ks2 * 2 + (grp >> 1);
            int cB = ks2 * 2 + selB;
#pragma unroll
            for (int mi = 0; mi < 4; mi++) {
                int row = wm + mi * 16 + (grp & 1) * 8 + lrow;
                ldsm_x4(af[mi], swadr(base, row, cA));
            }
#pragma unroll
            for (int ni = 0; ni < 4; ni++) {
                int row = wn + ni * 8 + lrB;
                uint32_t ad = swadr(base + 2 * TIL, row, cB);
                ldsm_x2(bf[ni], ad);
                ldsm_x2(bl2[ni], ad + TIL);
            }
#pragma unroll
            for (int mi = 0; mi < 4; mi++)
#pragma unroll
                for (int ni = 0; ni < 4; ni++) mma_bf16(acc[mi][ni], af[mi], bf[ni]);
#pragma unroll
            for (int mi = 0; mi < 4; mi++)
#pragma unroll
                for (int ni = 0; ni < 4; ni++) mma_bf16(acc[mi][ni], af[mi], bl2[ni]);
#pragma unroll
            for (int mi = 0; mi < 4; mi++) {
                int row = wm + mi * 16 + (grp & 1) * 8 + lrow;
                ldsm_x4(af[mi], swadr(base + TIL, row, cA));
            }
#pragma unroll
            for (int mi = 0; mi < 4; mi++)
#pragma unroll
                for (int ni = 0; ni < 4; ni++) mma_bf16(acc[mi][ni], af[mi], bf[ni]);
        }
    };

    load_stage(0, 0); CP_COMMIT();
    load_stage(1, 1); CP_COMMIT();
    for (int kb = 0; kb < KB; kb++) {
        if (kb + 1 < KB) { CP_WAIT(1); } else { CP_WAIT(0); }
        __syncthreads();
        if (kb + 2 < KB) { load_stage((kb + 2) % 3, kb + 2); CP_COMMIT(); }
        compute_stage(kb % 3);
    }
    __syncthreads();

    // transpose through smem -> coalesced [pixel][channel] stores
    float* Cs = reinterpret_cast<float*>(smbuf);
#pragma unroll
    for (int mi = 0; mi < 4; mi++)
#pragma unroll
        for (int ni = 0; ni < 4; ni++) {
            int rm = wm + mi * 16 + (lane >> 2);
            int cn = wn + ni * 8 + 2 * (lane & 3);
            Cs[cn * 132 + rm]           = acc[mi][ni][0];
            Cs[(cn + 1) * 132 + rm]     = acc[mi][ni][1];
            Cs[cn * 132 + rm + 8]       = acc[mi][ni][2];
            Cs[(cn + 1) * 132 + rm + 8] = acc[mi][ni][3];
        }
    __syncthreads();

    {
        int nl = tid >> 1, m0 = (tid & 1) * 64;
        int ng = nt * 128 + nl;
        int mg0 = mt * 128 + m0;
        if constexpr (EPI == 2 || EPI == 3) {
#pragma unroll
            for (int j0 = 0; j0 < 64; j0 += 8) {
                if (mg0 + j0 >= Mreal) break;
                union { __nv_bfloat16 h[8]; uint4 v; } ph, pl;
                float rv[8];
                if constexpr (EPI == 3) {
                    const float4* rp = reinterpret_cast<const float4*>(
                        resid + (size_t)ng * ldob + mg0 + j0);
                    float4 r0 = rp[0], r1 = rp[1];
                    rv[0]=r0.x; rv[1]=r0.y; rv[2]=r0.z; rv[3]=r0.w;
                    rv[4]=r1.x; rv[5]=r1.y; rv[6]=r1.z; rv[7]=r1.w;
                }
#pragma unroll
                for (int e = 0; e < 8; e++) {
                    int m = mg0 + j0 + e;
                    float v = Cs[nl * 132 + m0 + j0 + e];
                    float w = fmaxf(fmaf(sv[m], v, tv[m]), 0.f);
                    if constexpr (EPI == 3) w += rv[e];
                    split_bf(w, ph.h[e], pl.h[e]);
                }
                size_t o = (size_t)ng * ldob + mg0 + j0;
                *reinterpret_cast<uint4*>(ohi + o) = ph.v;
                *reinterpret_cast<uint4*>(olo + o) = pl.v;
            }
        } else {
#pragma unroll
            for (int j0 = 0; j0 < 64; j0 += 4) {
                if (mg0 + j0 >= Mreal) break;
                float4 ov;
                float* pv = reinterpret_cast<float*>(&ov);
#pragma unroll
                for (int e = 0; e < 4; e++) {
                    int m = mg0 + j0 + e;
                    float v = Cs[nl * 132 + m0 + j0 + e];
                    if constexpr (EPI == 1) v = fmaxf(fmaf(sv[m], v, tv[m]), 0.f);
                    if constexpr (EPI == 4) v = v + sv[m];
                    pv[e] = v;
                }
                *reinterpret_cast<float4*>(outf + (size_t)ng * ldo + mg0 + j0) = ov;
            }
        }
    }
}

// ---------------- launch ----------------
extern "C" void kernel_launch(void* const* d_in, const int* in_sizes, int n_in,
                              void* d_out, int out_size) {
    const float *x = (const float*)d_in[0], *pos2d = (const float*)d_in[1];
    const float *w_pos = (const float*)d_in[2], *b_pos = (const float*)d_in[3];
    const float *w_e = (const float*)d_in[4],  *w1 = (const float*)d_in[6];
    const float *w2 = (const float*)d_in[8],   *w_ag = (const float*)d_in[10];
    const float *w_ag_s = (const float*)d_in[12], *b_ag_s = (const float*)d_in[13];
    const float *w_att = (const float*)d_in[14], *w_att_s = (const float*)d_in[16];
    const float *b_att_s = (const float*)d_in[17], *Wsm = (const float*)d_in[18];
    float* out = (float*)d_out;

    float* F32 = nullptr;  __nv_bfloat16* B16 = nullptr;
    cudaGetSymbolAddress((void**)&F32, g_F32);
    cudaGetSymbolAddress((void**)&B16, g_B16);

    float *F = F32+OF_F, *P2 = F32+OF_P2, *WPT = F32+OF_WPT, *PP = F32+OF_PP;
    float *AB = F32+OF_AB, *H0F = F32+OF_H0F, *AG = F32+OF_AG, *FST = F32+OF_FST;
    float *ATTL = F32+OF_ATTL, *ATTS = F32+OF_ATTS, *SBN = F32+OF_SBN;

    cudaFuncSetAttribute(gemm_mma<0>, cudaFuncAttributeMaxDynamicSharedMemorySize, SMEMB);
    cudaFuncSetAttribute(gemm_mma<1>, cudaFuncAttributeMaxDynamicSharedMemorySize, SMEMB);
    cudaFuncSetAttribute(gemm_mma<2>, cudaFuncAttributeMaxDynamicSharedMemorySize, SMEMB);
    cudaFuncSetAttribute(gemm_mma<3>, cudaFuncAttributeMaxDynamicSharedMemorySize, SMEMB);
    cudaFuncSetAttribute(gemm_mma<4>, cudaFuncAttributeMaxDynamicSharedMemorySize, SMEMB);

    // ordered so launch #6 is the first big GEMM (ncu -s 5 -c 1)
    k_build_f<<<(P4_*68+255)/256, 256>>>(x, F, B16+OB_FBH, B16+OB_FBL);
    k_wprep<<<(2176*68+255)/256,256>>>(w_e, 0, 2176, 544, 2176, 3, B16+OB_WEH, B16+OB_WEL);
    k_bn_fold<<<(5*CIN_+255)/256, 256>>>((const float*)d_in[5], (const float*)d_in[7],
                                         (const float*)d_in[9], (const float*)d_in[11],
                                         (const float*)d_in[15], SBN);
    k_wposT<<<(PCH_*CIN_+255)/256, 256>>>(w_pos, WPT);
    k_build_p<<<(P4_*PCH_+255)/256, 256>>>(pos2d, P2);

    // layer 1 stacked: AB = [We_a; We_b] @ f   (M=2176, K=544)
    gemm_mma<0><<<dim3(17,32),256,SMEMB>>>(B16+OB_WEH,B16+OB_WEL, B16+OB_FBH,B16+OB_FBL,
                                           544, 17, 2176, AB, 2176, nullptr,nullptr,0,
                                           nullptr,nullptr,nullptr);
    k_pos<<<(P4_*CIN_+255)/256, 256>>>(WPT, P2, PP);
    k_h0<<<(P16_*136+255)/256, 256>>>(AB, PP, b_pos, SBN, H0F, B16+OB_H0H, B16+OB_H0L);

    // remaining weight preps
    k_wprep<<<(1152*136+255)/256,256>>>(w1,   CIN_, 1088, 1088, 1152, 0, B16+OB_W1H,  B16+OB_W1L);
    k_wprep<<<(1152*136+255)/256,256>>>(w2,   CIN_, 1088, 1088, 1152, 0, B16+OB_W2H,  B16+OB_W2L);
    k_wprep<<<(1152*136+255)/256,256>>>(w_ag, CIN_, 1088, 1088, 1152, 0, B16+OB_WAGH, B16+OB_WAGL);
    k_wprep<<<(1152*136+255)/256,256>>>(w_att,CIN_, 1088, 1088, 1152, 0, B16+OB_WATH, B16+OB_WATL);
    k_wprep<<<(640*136+255)/256,256>>>(w_ag_s, CIN_, 544, 1088, 640, 0, B16+OB_WSH, B16+OB_WSL);
    k_wprep<<<(1152*68+255)/256,256>>>(Wsm, 0, 1088, 544, 1152, 2, B16+OB_W01H, B16+OB_W01L);

    // trunk
    gemm_mma<2><<<dim3(9,128),256,SMEMB>>>(B16+OB_W1H,B16+OB_W1L, B16+OB_H0H,B16+OB_H0L,
                                           1088, 34, 1088, nullptr,0, B16+OB_H1H,B16+OB_H1L,CIN_,
                                           SBN+2*CIN_, SBN+3*CIN_, nullptr);
    gemm_mma<3><<<dim3(9,128),256,SMEMB>>>(B16+OB_W2H,B16+OB_W2L, B16+OB_H1H,B16+OB_H1L,
                                           1088, 34, 1088, nullptr,0, B16+OB_H2H,B16+OB_H2L,CIN_,
                                           SBN+4*CIN_, SBN+5*CIN_, H0F);
    // aggregation branch
    gemm_mma<2><<<dim3(9,128),256,SMEMB>>>(B16+OB_WAGH,B16+OB_WAGL, B16+OB_H2H,B16+OB_H2L,
                                           1088, 34, 1088, nullptr,0, B16+OB_GH,B16+OB_GL,CIN_,
                                           SBN+6*CIN_, SBN+7*CIN_, nullptr);
    gemm_mma<4><<<dim3(5,128),256,SMEMB>>>(B16+OB_WSH,B16+OB_WSL, B16+OB_GH,B16+OB_GL,
                                           1088, 34, 544, AG, C_, nullptr,nullptr,0,
                                           b_ag_s, nullptr, nullptr);
    // attention branch (reuses G buffers after ag_s consumed them)
    gemm_mma<2><<<dim3(9,128),256,SMEMB>>>(B16+OB_WATH,B16+OB_WATL, B16+OB_H2H,B16+OB_H2L,
                                           1088, 34, 1088, nullptr,0, B16+OB_GH,B16+OB_GL,CIN_,
                                           SBN+8*CIN_, SBN+9*CIN_, nullptr);
    k_attlogit<<<P16_/8, 256>>>(w_att_s, b_att_s, B16+OB_GH, B16+OB_GL, ATTL);
    k_softmax<<<(P4_+255)/256, 256>>>(ATTL, ATTS);

    // self/transfer stacked: FST = [W0^T; W1^T] @ f  (M=1088, K=544)
    gemm_mma<0><<<dim3(9,32),256,SMEMB>>>(B16+OB_W01H,B16+OB_W01L, B16+OB_FBH,B16+OB_FBL,
                                          544, 17, 1088, FST, CIN_, nullptr,nullptr,0,
                                          nullptr,nullptr,nullptr);

    k_fuse<<<(BT_*2176+255)/256, 256>>>(F, FST, AG, ATTS, out);
}

// round 6
// speedup vs baseline: 3.0994x; 1.0303x over previous
#include <cuda_runtime.h>
#include <cuda_bf16.h>
#include <stdint.h>
#include <math.h>

namespace fv {
constexpr int C_ = 544, CIN_ = 1088, BT_ = 1024, P4_ = 4096, P16_ = 16384, PCH_ = 34;

// fp32 scratch (elements)
constexpr size_t OF_F    = 0;                              // [P4][544]
constexpr size_t OF_P2   = OF_F    + (size_t)P4_*C_;       // [P4][34]
constexpr size_t OF_WPT  = OF_P2   + (size_t)P4_*PCH_;     // [34][1088]
constexpr size_t OF_PP   = OF_WPT  + (size_t)PCH_*CIN_;    // [P4][1088]
constexpr size_t OF_AB   = OF_PP   + (size_t)P4_*CIN_;     // [P4][2176]
constexpr size_t OF_AG   = OF_AB   + (size_t)P4_*2176;     // [P16][544]
constexpr size_t OF_FST  = OF_AG   + (size_t)P16_*C_;      // [P4][1088]
constexpr size_t OF_ATTL = OF_FST  + (size_t)P4_*CIN_;
constexpr size_t OF_ATTS = OF_ATTL + (size_t)P16_;
constexpr size_t OF_SBN  = OF_ATTS + (size_t)P16_;         // [5][2][1088]
constexpr size_t TOT_F32 = OF_SBN + (size_t)5*2*CIN_;

// bf16 row-major scratch [rows][K]
constexpr size_t SZ_FB  = (size_t)P4_ * C_;
constexpr size_t SZ_H   = (size_t)P16_ * CIN_;
constexpr size_t SZ_WE  = (size_t)2176 * 544;
constexpr size_t SZ_WB  = (size_t)1152 * 1088;
constexpr size_t SZ_WS  = (size_t)640 * 1088;
constexpr size_t SZ_W01 = (size_t)1152 * 544;

constexpr size_t OB_FBH  = 0;
constexpr size_t OB_FBL  = OB_FBH  + SZ_FB;
constexpr size_t OB_H0H  = OB_FBL  + SZ_FB;
constexpr size_t OB_H0L  = OB_H0H  + SZ_H;
constexpr size_t OB_H1H  = OB_H0L  + SZ_H;
constexpr size_t OB_H1L  = OB_H1H  + SZ_H;
constexpr size_t OB_H2H  = OB_H1L  + SZ_H;
constexpr size_t OB_H2L  = OB_H2H  + SZ_H;
constexpr size_t OB_GH   = OB_H2L  + SZ_H;
constexpr size_t OB_GL   = OB_GH   + SZ_H;
constexpr size_t OB_WEH  = OB_GL   + SZ_H;
constexpr size_t OB_WEL  = OB_WEH  + SZ_WE;
constexpr size_t OB_W1H  = OB_WEL  + SZ_WE;
constexpr size_t OB_W1L  = OB_W1H  + SZ_WB;
constexpr size_t OB_W2H  = OB_W1L  + SZ_WB;
constexpr size_t OB_W2L  = OB_W2H  + SZ_WB;
constexpr size_t OB_WAGH = OB_W2L  + SZ_WB;
constexpr size_t OB_WAGL = OB_WAGH + SZ_WB;
constexpr size_t OB_WATH = OB_WAGL + SZ_WB;
constexpr size_t OB_WATL = OB_WATH + SZ_WB;
constexpr size_t OB_WSH  = OB_WATL + SZ_WB;
constexpr size_t OB_WSL  = OB_WSH  + SZ_WS;
constexpr size_t OB_W01H = OB_WSL  + SZ_WS;
constexpr size_t OB_W01L = OB_W01H + SZ_W01;
constexpr size_t TOT_B16 = OB_W01L + SZ_W01;
}  // namespace fv

__device__ float         g_F32[fv::TOT_F32];
__device__ __nv_bfloat16 g_B16[fv::TOT_B16];

using namespace fv;

// ---------------- baseline-PTX helpers ----------------
__device__ __forceinline__ uint32_t smem_u32(const void* p) {
    uint32_t a;
    asm("{ .reg .u64 t; cvta.to.shared.u64 t, %1; cvt.u32.u64 %0, t; }" : "=r"(a) : "l"(p));
    return a;
}
__device__ __forceinline__ void cp16(uint32_t dst, const void* src) {
    asm volatile("cp.async.cg.shared.global [%0], [%1], 16;" :: "r"(dst), "l"(src));
}
#define CP_COMMIT() asm volatile("cp.async.commit_group;" ::: "memory")
#define CP_WAIT(n)  asm volatile("cp.async.wait_group %0;" :: "n"(n) : "memory")

__device__ __forceinline__ void ldsm_x4(uint32_t (&r)[4], uint32_t addr) {
    asm volatile("ldmatrix.sync.aligned.m8n8.x4.shared.b16 {%0,%1,%2,%3}, [%4];"
                 : "=r"(r[0]), "=r"(r[1]), "=r"(r[2]), "=r"(r[3]) : "r"(addr));
}
__device__ __forceinline__ void mma_bf16(float (&d)[4], const uint32_t (&a)[4],
                                         const uint32_t (&b)[2]) {
    asm volatile(
        "mma.sync.aligned.m16n8k16.row.col.f32.bf16.bf16.f32 "
        "{%0,%1,%2,%3}, {%4,%5,%6,%7}, {%8,%9}, {%0,%1,%2,%3};"
        : "+f"(d[0]), "+f"(d[1]), "+f"(d[2]), "+f"(d[3])
        : "r"(a[0]), "r"(a[1]), "r"(a[2]), "r"(a[3]), "r"(b[0]), "r"(b[1]));
}
__device__ __forceinline__ void split_bf(float v, __nv_bfloat16& h, __nv_bfloat16& l) {
    h = __float2bfloat16(v);
    l = __float2bfloat16(v - __bfloat162float(h));
}

// ---------------- prep / elementwise ----------------
__global__ void k_bn_fold(const float* __restrict__ b0, const float* __restrict__ b1,
                          const float* __restrict__ b2, const float* __restrict__ b3,
                          const float* __restrict__ b4, float* __restrict__ sbn) {
    int idx = blockIdx.x * blockDim.x + threadIdx.x;
    if (idx >= 5 * CIN_) return;
    int w = idx / CIN_, c = idx % CIN_;
    const float* bn = w == 0 ? b0 : w == 1 ? b1 : w == 2 ? b2 : w == 3 ? b3 : b4;
    float s = bn[c] * rsqrtf(bn[3 * CIN_ + c] + 1e-5f);
    sbn[w * 2 * CIN_ + c] = s;
    sbn[w * 2 * CIN_ + CIN_ + c] = bn[CIN_ + c] - bn[2 * CIN_ + c] * s;
}

__global__ void k_wposT(const float* __restrict__ wpos, float* __restrict__ wpt) {
    int idx = blockIdx.x * blockDim.x + threadIdx.x;
    if (idx >= PCH_ * CIN_) return;
    int k = idx / CIN_, o = idx % CIN_;
    wpt[idx] = wpos[o * PCH_ + k];
}

// weight -> padded row-major [MP][K] bf16 hi/lo.
// mode 0: src[r*ld + k]
// mode 2: stacked Wsm^T: src[(r/544)*295936 + k*544 + (r%544)]
// mode 3: stacked We:    src[(r%1088)*1088 + (r/1088)*544 + k]
__global__ void k_wprep(const float* __restrict__ src, int ld, int Msrc, int K,
                        int MP, int mode,
                        __nv_bfloat16* __restrict__ hi, __nv_bfloat16* __restrict__ lo) {
    int K8 = K >> 3;
    int idx = blockIdx.x * blockDim.x + threadIdx.x;
    if (idx >= MP * K8) return;
    int r = idx / K8, k0 = (idx % K8) * 8;
    union { __nv_bfloat16 h[8]; uint4 v; } ph, pl;
#pragma unroll
    for (int e = 0; e < 8; e++) {
        int k = k0 + e;
        float x = 0.f;
        if (r < Msrc) {
            if (mode == 0)      x = src[(size_t)r * ld + k];
            else if (mode == 2) x = src[(size_t)(r / 544) * 295936 + (size_t)k * 544 + (r % 544)];
            else                x = src[(size_t)(r % 1088) * 1088 + (size_t)(r / 1088) * 544 + k];
        }
        split_bf(x, ph.h[e], pl.h[e]);
    }
    size_t o = (size_t)r * K + k0;
    *reinterpret_cast<uint4*>(hi + o) = ph.v;
    *reinterpret_cast<uint4*>(lo + o) = pl.v;
}

__global__ void k_build_f(const float* __restrict__ x, float* __restrict__ F,
                          __nv_bfloat16* __restrict__ fh, __nv_bfloat16* __restrict__ fl) {
    int idx = blockIdx.x * blockDim.x + threadIdx.x;
    if (idx >= P4_ * 68) return;
    int p = idx / 68, c0 = (idx % 68) * 8;
    int bt = p >> 2, n = p & 3;
    union { __nv_bfloat16 h[8]; uint4 v; } ph, pl;
    float vv[8];
#pragma unroll
    for (int e = 0; e < 8; e++) {
        vv[e] = x[((size_t)bt * C_ + c0 + e) * 4 + n];
        split_bf(vv[e], ph.h[e], pl.h[e]);
    }
    size_t o = (size_t)p * C_ + c0;
    *reinterpret_cast<uint4*>(fh + o) = ph.v;
    *reinterpret_cast<uint4*>(fl + o) = pl.v;
    float4* d = reinterpret_cast<float4*>(F + o);
    d[0] = make_float4(vv[0], vv[1], vv[2], vv[3]);
    d[1] = make_float4(vv[4], vv[5], vv[6], vv[7]);
}

__global__ void k_build_p(const float* __restrict__ pos, float* __restrict__ P2) {
    int idx = blockIdx.x * blockDim.x + threadIdx.x;
    if (idx >= P4_ * PCH_) return;
    int p = idx / PCH_, k = idx % PCH_;
    P2[idx] = pos[((size_t)(p >> 2) * PCH_ + k) * 4 + (p & 3)];
}

__global__ void k_pos(const float* __restrict__ wpt, const float* __restrict__ P2,
                      float* __restrict__ PP) {
    int idx = blockIdx.x * blockDim.x + threadIdx.x;
    if (idx >= P4_ * CIN_) return;
    int p = idx / CIN_, o = idx % CIN_;
    float acc = 0.f;
#pragma unroll
    for (int k = 0; k < PCH_; k++) acc = fmaf(wpt[k * CIN_ + o], P2[p * PCH_ + k], acc);
    PP[idx] = acc;
}

__global__ void k_h0(const float* __restrict__ AB, const float* __restrict__ PP,
                     const float* __restrict__ bpos, const float* __restrict__ sbn,
                     __nv_bfloat16* __restrict__ hh, __nv_bfloat16* __restrict__ hl) {
    int idx = blockIdx.x * blockDim.x + threadIdx.x;
    if (idx >= P16_ * 136) return;
    int p16 = idx / 136, o0 = (idx % 136) * 8;
    int bt = p16 >> 4, ij = p16 & 15, i = ij >> 2, j = ij & 3;
    size_t pa = (size_t)(bt * 4 + i) * 2176 + o0;
    size_t pb = (size_t)(bt * 4 + j) * 2176 + 1088 + o0;
    size_t qi = (size_t)(bt * 4 + i) * CIN_ + o0;
    size_t qj = (size_t)(bt * 4 + j) * CIN_ + o0;
    union { __nv_bfloat16 h[8]; uint4 v; } ph, pl;
#pragma unroll
    for (int e = 0; e < 8; e++) {
        int o = o0 + e;
        float v = fmaxf(fmaf(sbn[o], AB[pa + e] + AB[pb + e], sbn[CIN_ + o]), 0.f);
        v += PP[qi + e] - PP[qj + e] + bpos[o];
        split_bf(v, ph.h[e], pl.h[e]);
    }
    size_t o = (size_t)p16 * CIN_ + o0;
    *reinterpret_cast<uint4*>(hh + o) = ph.v;
    *reinterpret_cast<uint4*>(hl + o) = pl.v;
}

__global__ void k_attl_init(const float* __restrict__ b, float* __restrict__ L) {
    int p = blockIdx.x * blockDim.x + threadIdx.x;
    if (p < P16_) L[p] = b[0];
}

__global__ void k_softmax(const float* __restrict__ L, float* __restrict__ S) {
    int r = blockIdx.x * blockDim.x + threadIdx.x;
    if (r >= P4_) return;
    float l0 = L[r*4], l1 = L[r*4+1], l2 = L[r*4+2], l3 = L[r*4+3];
    float m = fmaxf(fmaxf(l0, l1), fmaxf(l2, l3));
    float e0 = __expf(l0-m), e1 = __expf(l1-m), e2 = __expf(l2-m), e3 = __expf(l3-m);
    float inv = 1.f / (e0+e1+e2+e3);
    S[r*4]=e0*inv; S[r*4+1]=e1*inv; S[r*4+2]=e2*inv; S[r*4+3]=e3*inv;
}

__global__ void k_fuse(const float* __restrict__ F, const float* __restrict__ FST,
                       const float* __restrict__ AG, const float* __restrict__ S,
                       float* __restrict__ out) {
    int idx = blockIdx.x * blockDim.x + threadIdx.x;
    if (idx >= BT_ * 2176) return;
    int bt = idx / 2176, rem = idx % 2176;
    int i = rem / C_, d = rem % C_;
    int ri = bt * 4 + i;
    float acc = F[(size_t)ri * C_ + d];
#pragma unroll
    for (int j = 0; j < 4; j++) {
        float a = S[ri * 4 + j];
        if (j == i) acc = fmaf(FST[(size_t)ri * CIN_ + d], a, acc);
        else acc = fmaf(FST[(size_t)(bt*4+j) * CIN_ + 544 + d] *
                        AG[(size_t)(bt*16+i*4+j) * C_ + d], a, acc);
    }
    out[(size_t)bt * 2176 + d * 4 + i] = acc;
}

// ---------------- HMMA split-bf16 GEMM ----------------
// C[m=outch][n=pixel] = W[MP][K] @ X[NP][K]^T. 3 passes: AhBh + AhBl + AlBh.
// EPI: 0 fp32 | 2 relu->bf16 h/l | 3 bf16resid+relu->bf16 | 4 v+bias fp32 | 5 att-dot atomic
constexpr int TIL = 8192;        // 128 rows x 64B
constexpr int STG = 4 * TIL;     // Ah|Al|Bh|Bl = 32 KB
constexpr int SMEMB = 3 * STG;   // 96 KB

__device__ __forceinline__ uint32_t swadr(uint32_t base, int row, int c16) {
    return base + row * 64 + ((c16 ^ ((row >> 1) & 3)) << 4);
}

template <int EPI>
__global__ void __launch_bounds__(256, 2)
gemm_mma(const __nv_bfloat16* __restrict__ Ahg, const __nv_bfloat16* __restrict__ Alg,
         const __nv_bfloat16* __restrict__ Bhg, const __nv_bfloat16* __restrict__ Blg,
         int K, int KB, int Mreal,
         float* __restrict__ outf, int ldo,
         __nv_bfloat16* __restrict__ ohi, __nv_bfloat16* __restrict__ olo, int ldob,
         const float* __restrict__ sv, const float* __restrict__ tv,
         const __nv_bfloat16* __restrict__ rhi, const __nv_bfloat16* __restrict__ rlo,
         const float* __restrict__ watt) {
    extern __shared__ __nv_bfloat16 smbuf[];
    const uint32_t sb = smem_u32(smbuf);
    const int tid = threadIdx.x, lane = tid & 31, wid = tid >> 5;
    const int mt = blockIdx.x, nt = blockIdx.y;
    const int wm = (wid >> 2) * 64, wn = (wid & 3) * 32;

    float acc[4][4][4];
#pragma unroll
    for (int a = 0; a < 4; a++)
#pragma unroll
        for (int b = 0; b < 4; b++)
#pragma unroll
            for (int c = 0; c < 4; c++) acc[a][b][c] = 0.f;

    auto load_stage = [&](int s, int kb) {
        uint32_t dstb = sb + s * STG;
        int k0 = kb * 32;
#pragma unroll
        for (int c = 0; c < 2; c++) {
            int q = tid + c * 256;
            int r = q >> 2, ch = q & 3;
            uint32_t d = dstb + r * 64 + ((ch ^ ((r >> 1) & 3)) << 4);
            size_t offA = (size_t)(mt * 128 + r) * K + k0 + ch * 8;
            size_t offB = (size_t)(nt * 128 + r) * K + k0 + ch * 8;
            cp16(d,           Ahg + offA);
            cp16(d + TIL,     Alg + offA);
            cp16(d + 2 * TIL, Bhg + offB);
            cp16(d + 3 * TIL, Blg + offB);
        }
    };

    const int grp = lane >> 3, lrow = lane & 7;

    auto compute_stage = [&](int s) {
        uint32_t base = sb + s * STG;
#pragma unroll
        for (int ks2 = 0; ks2 < 2; ks2++) {
            uint32_t af[4][4], bf[4][2], bl2[4][2];
            const int cA = ks2 * 2 + (grp >> 1);
            const int cB = ks2 * 2 + (grp & 1);
#pragma unroll
            for (int mi = 0; mi < 4; mi++) {
                int row = wm + mi * 16 + (grp & 1) * 8 + lrow;
                ldsm_x4(af[mi], swadr(base, row, cA));
            }
#pragma unroll
            for (int n2 = 0; n2 < 2; n2++) {
                int row = wn + n2 * 16 + (grp >> 1) * 8 + lrow;
                uint32_t q[4];
                ldsm_x4(q, swadr(base + 2 * TIL, row, cB));
                bf[n2 * 2][0] = q[0]; bf[n2 * 2][1] = q[1];
                bf[n2 * 2 + 1][0] = q[2]; bf[n2 * 2 + 1][1] = q[3];
                ldsm_x4(q, swadr(base + 3 * TIL, row, cB));
                bl2[n2 * 2][0] = q[0]; bl2[n2 * 2][1] = q[1];
                bl2[n2 * 2 + 1][0] = q[2]; bl2[n2 * 2 + 1][1] = q[3];
            }
#pragma unroll
            for (int mi = 0; mi < 4; mi++)
#pragma unroll
                for (int ni = 0; ni < 4; ni++) mma_bf16(acc[mi][ni], af[mi], bf[ni]);
#pragma unroll
            for (int mi = 0; mi < 4; mi++)
#pragma unroll
                for (int ni = 0; ni < 4; ni++) mma_bf16(acc[mi][ni], af[mi], bl2[ni]);
#pragma unroll
            for (int mi = 0; mi < 4; mi++) {
                int row = wm + mi * 16 + (grp & 1) * 8 + lrow;
                ldsm_x4(af[mi], swadr(base + TIL, row, cA));
            }
#pragma unroll
            for (int mi = 0; mi < 4; mi++)
#pragma unroll
                for (int ni = 0; ni < 4; ni++) mma_bf16(acc[mi][ni], af[mi], bf[ni]);
        }
    };

    load_stage(0, 0); CP_COMMIT();
    load_stage(1, 1); CP_COMMIT();
    for (int kb = 0; kb < KB; kb++) {
        if (kb + 1 < KB) { CP_WAIT(1); } else { CP_WAIT(0); }
        __syncthreads();
        if (kb + 2 < KB) { load_stage((kb + 2) % 3, kb + 2); CP_COMMIT(); }
        compute_stage(kb % 3);
    }
    __syncthreads();

    // transpose through smem
    float* Cs = reinterpret_cast<float*>(smbuf);
#pragma unroll
    for (int mi = 0; mi < 4; mi++)
#pragma unroll
        for (int ni = 0; ni < 4; ni++) {
            int rm = wm + mi * 16 + (lane >> 2);
            int cn = wn + ni * 8 + 2 * (lane & 3);
            Cs[cn * 132 + rm]           = acc[mi][ni][0];
            Cs[(cn + 1) * 132 + rm]     = acc[mi][ni][1];
            Cs[cn * 132 + rm + 8]       = acc[mi][ni][2];
            Cs[(cn + 1) * 132 + rm + 8] = acc[mi][ni][3];
        }
    __syncthreads();

    {
        int nl = tid >> 1, m0 = (tid & 1) * 64;
        int ng = nt * 128 + nl;
        int mg0 = mt * 128 + m0;
        if constexpr (EPI == 5) {
            float wsum = 0.f;
#pragma unroll 8
            for (int j = 0; j < 64; j++) {
                int m = mg0 + j;
                if (m >= Mreal) break;
                float v = Cs[nl * 132 + m0 + j];
                wsum = fmaf(fmaxf(fmaf(sv[m], v, tv[m]), 0.f), watt[m], wsum);
            }
            atomicAdd(&outf[ng], wsum);
        } else if constexpr (EPI == 2 || EPI == 3) {
#pragma unroll
            for (int j0 = 0; j0 < 64; j0 += 8) {
                if (mg0 + j0 >= Mreal) break;
                union { __nv_bfloat16 h[8]; uint4 v; } ph, pl;
                float rv[8];
                if constexpr (EPI == 3) {
                    size_t o = (size_t)ng * ldob + mg0 + j0;
                    uint4 rh4 = *reinterpret_cast<const uint4*>(rhi + o);
                    uint4 rl4 = *reinterpret_cast<const uint4*>(rlo + o);
                    const __nv_bfloat16* rh = reinterpret_cast<const __nv_bfloat16*>(&rh4);
                    const __nv_bfloat16* rl = reinterpret_cast<const __nv_bfloat16*>(&rl4);
#pragma unroll
                    for (int e = 0; e < 8; e++)
                        rv[e] = __bfloat162float(rh[e]) + __bfloat162float(rl[e]);
                }
#pragma unroll
                for (int e = 0; e < 8; e++) {
                    int m = mg0 + j0 + e;
                    float v = Cs[nl * 132 + m0 + j0 + e];
                    float w = fmaxf(fmaf(sv[m], v, tv[m]), 0.f);
                    if constexpr (EPI == 3) w += rv[e];
                    split_bf(w, ph.h[e], pl.h[e]);
                }
                size_t o = (size_t)ng * ldob + mg0 + j0;
                *reinterpret_cast<uint4*>(ohi + o) = ph.v;
                *reinterpret_cast<uint4*>(olo + o) = pl.v;
            }
        } else {
#pragma unroll
            for (int j0 = 0; j0 < 64; j0 += 4) {
                if (mg0 + j0 >= Mreal) break;
                float4 ov;
                float* pv = reinterpret_cast<float*>(&ov);
#pragma unroll
                for (int e = 0; e < 4; e++) {
                    int m = mg0 + j0 + e;
                    float v = Cs[nl * 132 + m0 + j0 + e];
                    if constexpr (EPI == 4) v = v + sv[m];
                    pv[e] = v;
                }
                *reinterpret_cast<float4*>(outf + (size_t)ng * ldo + mg0 + j0) = ov;
            }
        }
    }
}

// ---------------- launch ----------------
extern "C" void kernel_launch(void* const* d_in, const int* in_sizes, int n_in,
                              void* d_out, int out_size) {
    const float *x = (const float*)d_in[0], *pos2d = (const float*)d_in[1];
    const float *w_pos = (const float*)d_in[2], *b_pos = (const float*)d_in[3];
    const float *w_e = (const float*)d_in[4],  *w1 = (const float*)d_in[6];
    const float *w2 = (const float*)d_in[8],   *w_ag = (const float*)d_in[10];
    const float *w_ag_s = (const float*)d_in[12], *b_ag_s = (const float*)d_in[13];
    const float *w_att = (const float*)d_in[14], *w_att_s = (const float*)d_in[16];
    const float *b_att_s = (const float*)d_in[17], *Wsm = (const float*)d_in[18];
    float* out = (float*)d_out;

    float* F32 = nullptr;  __nv_bfloat16* B16 = nullptr;
    cudaGetSymbolAddress((void**)&F32, g_F32);
    cudaGetSymbolAddress((void**)&B16, g_B16);

    float *F = F32+OF_F, *P2 = F32+OF_P2, *WPT = F32+OF_WPT, *PP = F32+OF_PP;
    float *AB = F32+OF_AB, *AG = F32+OF_AG, *FST = F32+OF_FST;
    float *ATTL = F32+OF_ATTL, *ATTS = F32+OF_ATTS, *SBN = F32+OF_SBN;

    cudaFuncSetAttribute(gemm_mma<0>, cudaFuncAttributeMaxDynamicSharedMemorySize, SMEMB);
    cudaFuncSetAttribute(gemm_mma<2>, cudaFuncAttributeMaxDynamicSharedMemorySize, SMEMB);
    cudaFuncSetAttribute(gemm_mma<3>, cudaFuncAttributeMaxDynamicSharedMemorySize, SMEMB);
    cudaFuncSetAttribute(gemm_mma<4>, cudaFuncAttributeMaxDynamicSharedMemorySize, SMEMB);
    cudaFuncSetAttribute(gemm_mma<5>, cudaFuncAttributeMaxDynamicSharedMemorySize, SMEMB);

    k_build_f<<<(P4_*68+255)/256, 256>>>(x, F, B16+OB_FBH, B16+OB_FBL);
    k_wprep<<<(2176*68+255)/256,256>>>(w_e, 0, 2176, 544, 2176, 3, B16+OB_WEH, B16+OB_WEL);
    k_bn_fold<<<(5*CIN_+255)/256, 256>>>((const float*)d_in[5], (const float*)d_in[7],
                                         (const float*)d_in[9], (const float*)d_in[11],
                                         (const float*)d_in[15], SBN);
    k_wposT<<<(PCH_*CIN_+255)/256, 256>>>(w_pos, WPT);
    k_build_p<<<(P4_*PCH_+255)/256, 256>>>(pos2d, P2);

    // layer 1 stacked: AB = [We_a; We_b] @ f
    gemm_mma<0><<<dim3(17,32),256,SMEMB>>>(B16+OB_WEH,B16+OB_WEL, B16+OB_FBH,B16+OB_FBL,
                                           544, 17, 2176, AB, 2176, nullptr,nullptr,0,
                                           nullptr,nullptr, nullptr,nullptr, nullptr);
    k_pos<<<(P4_*CIN_+255)/256, 256>>>(WPT, P2, PP);
    k_h0<<<(P16_*136+255)/256, 256>>>(AB, PP, b_pos, SBN, B16+OB_H0H, B16+OB_H0L);

    k_wprep<<<(1152*136+255)/256,256>>>(w1,   CIN_, 1088, 1088, 1152, 0, B16+OB_W1H,  B16+OB_W1L);
    k_wprep<<<(1152*136+255)/256,256>>>(w2,   CIN_, 1088, 1088, 1152, 0, B16+OB_W2H,  B16+OB_W2L);
    k_wprep<<<(1152*136+255)/256,256>>>(w_ag, CIN_, 1088, 1088, 1152, 0, B16+OB_WAGH, B16+OB_WAGL);
    k_wprep<<<(1152*136+255)/256,256>>>(w_att,CIN_, 1088, 1088, 1152, 0, B16+OB_WATH, B16+OB_WATL);
    k_wprep<<<(640*136+255)/256,256>>>(w_ag_s, CIN_, 544, 1088, 640, 0, B16+OB_WSH, B16+OB_WSL);
    k_wprep<<<(1152*68+255)/256,256>>>(Wsm, 0, 1088, 544, 1152, 2, B16+OB_W01H, B16+OB_W01L);

    // trunk
    gemm_mma<2><<<dim3(9,128),256,SMEMB>>>(B16+OB_W1H,B16+OB_W1L, B16+OB_H0H,B16+OB_H0L,
                                           1088, 34, 1088, nullptr,0, B16+OB_H1H,B16+OB_H1L,CIN_,
                                           SBN+2*CIN_, SBN+3*CIN_, nullptr,nullptr, nullptr);
    gemm_mma<3><<<dim3(9,128),256,SMEMB>>>(B16+OB_W2H,B16+OB_W2L, B16+OB_H1H,B16+OB_H1L,
                                           1088, 34, 1088, nullptr,0, B16+OB_H2H,B16+OB_H2L,CIN_,
                                           SBN+4*CIN_, SBN+5*CIN_, B16+OB_H0H,B16+OB_H0L, nullptr);
    // aggregation branch
    gemm_mma<2><<<dim3(9,128),256,SMEMB>>>(B16+OB_WAGH,B16+OB_WAGL, B16+OB_H2H,B16+OB_H2L,
                                           1088, 34, 1088, nullptr,0, B16+OB_GH,B16+OB_GL,CIN_,
                                           SBN+6*CIN_, SBN+7*CIN_, nullptr,nullptr, nullptr);
    gemm_mma<4><<<dim3(5,128),256,SMEMB>>>(B16+OB_WSH,B16+OB_WSL, B16+OB_GH,B16+OB_GL,
                                           1088, 34, 544, AG, C_, nullptr,nullptr,0,
                                           b_ag_s, nullptr, nullptr,nullptr, nullptr);
    // attention branch: logits fused into the GEMM epilogue
    k_attl_init<<<(P16_+255)/256, 256>>>(b_att_s, ATTL);
    gemm_mma<5><<<dim3(9,128),256,SMEMB>>>(B16+OB_WATH,B16+OB_WATL, B16+OB_H2H,B16+OB_H2L,
                                           1088, 34, 1088, ATTL, 0, nullptr,nullptr,0,
                                           SBN+8*CIN_, SBN+9*CIN_, nullptr,nullptr, w_att_s);
    k_softmax<<<(P4_+255)/256, 256>>>(ATTL, ATTS);

    // self/transfer stacked: FST = [W0^T; W1^T] @ f
    gemm_mma<0><<<dim3(9,32),256,SMEMB>>>(B16+OB_W01H,B16+OB_W01L, B16+OB_FBH,B16+OB_FBL,
                                          544, 17, 1088, FST, CIN_, nullptr,nullptr,0,
                                          nullptr,nullptr, nullptr,nullptr, nullptr);

    k_fuse<<<(BT_*2176+255)/256, 256>>>(F, FST, AG, ATTS, out);
}

// round 7
// speedup vs baseline: 4.1581x; 1.3416x over previous
#include <cuda_runtime.h>
#include <cuda_fp16.h>
#include <stdint.h>
#include <math.h>

namespace fv {
constexpr int C_ = 544, CIN_ = 1088, BT_ = 1024, P4_ = 4096, P16_ = 16384, PCH_ = 34;

// fp32 scratch (elements)
constexpr size_t OF_F    = 0;                              // [P4][544]
constexpr size_t OF_P2   = OF_F    + (size_t)P4_*C_;
constexpr size_t OF_WPT  = OF_P2   + (size_t)P4_*PCH_;
constexpr size_t OF_PP   = OF_WPT  + (size_t)PCH_*CIN_;
constexpr size_t OF_AB   = OF_PP   + (size_t)P4_*CIN_;     // [P4][2176]
constexpr size_t OF_AG   = OF_AB   + (size_t)P4_*2176;     // [P16][544]
constexpr size_t OF_FST  = OF_AG   + (size_t)P16_*C_;      // [P4][1088]
constexpr size_t OF_ATTL = OF_FST  + (size_t)P4_*CIN_;
constexpr size_t OF_ATTS = OF_ATTL + (size_t)P16_;
constexpr size_t OF_SBN  = OF_ATTS + (size_t)P16_;         // [5][2][1088]
// per-row weight scales
constexpr size_t OF_RSWE = OF_SBN  + (size_t)5*2*CIN_;     // 2176
constexpr size_t OF_RSW1 = OF_RSWE + 2176;                 // 1152
constexpr size_t OF_RSW2 = OF_RSW1 + 1152;
constexpr size_t OF_RSAG = OF_RSW2 + 1152;
constexpr size_t OF_RSAT = OF_RSAG + 1152;
constexpr size_t OF_RSWS = OF_RSAT + 1152;                 // 640
constexpr size_t OF_RS01 = OF_RSWS + 640;                  // 1152
constexpr size_t TOT_F32 = OF_RS01 + 1152;

// fp16 row-major scratch [rows][K]
constexpr size_t SZ_FB  = (size_t)P4_ * C_;
constexpr size_t SZ_H   = (size_t)P16_ * CIN_;
constexpr size_t SZ_WE  = (size_t)2176 * 544;
constexpr size_t SZ_WB  = (size_t)1152 * 1088;
constexpr size_t SZ_WS  = (size_t)640 * 1088;
constexpr size_t SZ_W01 = (size_t)1152 * 544;

constexpr size_t OB_FB   = 0;
constexpr size_t OB_H0   = OB_FB   + SZ_FB;
constexpr size_t OB_H1   = OB_H0   + SZ_H;
constexpr size_t OB_H2   = OB_H1   + SZ_H;
constexpr size_t OB_G    = OB_H2   + SZ_H;
constexpr size_t OB_WEH  = OB_G    + SZ_H;
constexpr size_t OB_WEL  = OB_WEH  + SZ_WE;
constexpr size_t OB_W1H  = OB_WEL  + SZ_WE;
constexpr size_t OB_W1L  = OB_W1H  + SZ_WB;
constexpr size_t OB_W2H  = OB_W1L  + SZ_WB;
constexpr size_t OB_W2L  = OB_W2H  + SZ_WB;
constexpr size_t OB_WAGH = OB_W2L  + SZ_WB;
constexpr size_t OB_WAGL = OB_WAGH + SZ_WB;
constexpr size_t OB_WATH = OB_WAGL + SZ_WB;
constexpr size_t OB_WATL = OB_WATH + SZ_WB;
constexpr size_t OB_WSH  = OB_WATL + SZ_WB;
constexpr size_t OB_WSL  = OB_WSH  + SZ_WS;
constexpr size_t OB_W01H = OB_WSL  + SZ_WS;
constexpr size_t OB_W01L = OB_W01H + SZ_W01;
constexpr size_t TOT_H16 = OB_W01L + SZ_W01;
}  // namespace fv

__device__ float  g_F32[fv::TOT_F32];
__device__ __half g_H16[fv::TOT_H16];

using namespace fv;

// ---------------- baseline-PTX helpers ----------------
__device__ __forceinline__ uint32_t smem_u32(const void* p) {
    uint32_t a;
    asm("{ .reg .u64 t; cvta.to.shared.u64 t, %1; cvt.u32.u64 %0, t; }" : "=r"(a) : "l"(p));
    return a;
}
__device__ __forceinline__ void cp16(uint32_t dst, const void* src) {
    asm volatile("cp.async.cg.shared.global [%0], [%1], 16;" :: "r"(dst), "l"(src));
}
#define CP_COMMIT() asm volatile("cp.async.commit_group;" ::: "memory")
#define CP_WAIT(n)  asm volatile("cp.async.wait_group %0;" :: "n"(n) : "memory")

__device__ __forceinline__ void ldsm_x4(uint32_t (&r)[4], uint32_t addr) {
    asm volatile("ldmatrix.sync.aligned.m8n8.x4.shared.b16 {%0,%1,%2,%3}, [%4];"
                 : "=r"(r[0]), "=r"(r[1]), "=r"(r[2]), "=r"(r[3]) : "r"(addr));
}
__device__ __forceinline__ void mma_f16(float (&d)[4], const uint32_t (&a)[4],
                                        const uint32_t (&b)[2]) {
    asm volatile(
        "mma.sync.aligned.m16n8k16.row.col.f32.f16.f16.f32 "
        "{%0,%1,%2,%3}, {%4,%5,%6,%7}, {%8,%9}, {%0,%1,%2,%3};"
        : "+f"(d[0]), "+f"(d[1]), "+f"(d[2]), "+f"(d[3])
        : "r"(a[0]), "r"(a[1]), "r"(a[2]), "r"(a[3]), "r"(b[0]), "r"(b[1]));
}

// ---------------- prep / elementwise ----------------
__global__ void k_bn_fold(const float* __restrict__ b0, const float* __restrict__ b1,
                          const float* __restrict__ b2, const float* __restrict__ b3,
                          const float* __restrict__ b4, float* __restrict__ sbn) {
    int idx = blockIdx.x * blockDim.x + threadIdx.x;
    if (idx >= 5 * CIN_) return;
    int w = idx / CIN_, c = idx % CIN_;
    const float* bn = w == 0 ? b0 : w == 1 ? b1 : w == 2 ? b2 : w == 3 ? b3 : b4;
    float s = bn[c] * rsqrtf(bn[3 * CIN_ + c] + 1e-5f);
    sbn[w * 2 * CIN_ + c] = s;
    sbn[w * 2 * CIN_ + CIN_ + c] = bn[CIN_ + c] - bn[2 * CIN_ + c] * s;
}

__global__ void k_wposT(const float* __restrict__ wpos, float* __restrict__ wpt) {
    int idx = blockIdx.x * blockDim.x + threadIdx.x;
    if (idx >= PCH_ * CIN_) return;
    int k = idx / CIN_, o = idx % CIN_;
    wpt[idx] = wpos[o * PCH_ + k];
}

// weight addressing modes:
// 0: src[r*ld + k]
// 2: stacked Wsm^T: src[(r/544)*295936 + k*544 + (r%544)]
// 3: stacked We:    src[(r%1088)*1088 + (r/1088)*544 + k]
__device__ __forceinline__ float wsrc(const float* src, int ld, int mode, int r, int k) {
    if (mode == 0) return src[(size_t)r * ld + k];
    if (mode == 2) return src[(size_t)(r / 544) * 295936 + (size_t)k * 544 + (r % 544)];
    return src[(size_t)(r % 1088) * 1088 + (size_t)(r / 1088) * 544 + k];
}

// per-row power-of-2 scale: rs[r] = 2^e with rowmax/2^e in [0.5,1)
__global__ void k_wscale(const float* __restrict__ src, int ld, int Msrc, int K,
                         int MP, int mode, float* __restrict__ rs) {
    int w = threadIdx.x >> 5, lane = threadIdx.x & 31;
    int r = blockIdx.x * 8 + w;
    if (r >= MP) return;
    float mx = 0.f;
    if (r < Msrc)
        for (int k = lane; k < K; k += 32) mx = fmaxf(mx, fabsf(wsrc(src, ld, mode, r, k)));
#pragma unroll
    for (int o = 16; o > 0; o >>= 1) mx = fmaxf(mx, __shfl_xor_sync(0xFFFFFFFFu, mx, o));
    if (lane == 0) {
        int e = 0;
        if (mx > 0.f) frexpf(mx, &e);
        rs[r] = exp2f((float)e);
    }
}

// weight -> padded row-major [MP][K] fp16 hi/lo, scaled by 1/rs[r]
__global__ void k_wprep(const float* __restrict__ src, int ld, int Msrc, int K,
                        int MP, int mode, const float* __restrict__ rs,
                        __half* __restrict__ hi, __half* __restrict__ lo) {
    int K8 = K >> 3;
    int idx = blockIdx.x * blockDim.x + threadIdx.x;
    if (idx >= MP * K8) return;
    int r = idx / K8, k0 = (idx % K8) * 8;
    float inv = 1.0f / rs[r];
    union { __half h[8]; uint4 v; } ph, pl;
#pragma unroll
    for (int e = 0; e < 8; e++) {
        float x = (r < Msrc) ? wsrc(src, ld, mode, r, k0 + e) * inv : 0.f;
        __half h = __float2half(x);
        ph.h[e] = h;
        pl.h[e] = __float2half(x - __half2float(h));
    }
    size_t o = (size_t)r * K + k0;
    *reinterpret_cast<uint4*>(hi + o) = ph.v;
    *reinterpret_cast<uint4*>(lo + o) = pl.v;
}

__global__ void k_build_f(const float* __restrict__ x, float* __restrict__ F,
                          __half* __restrict__ fb) {
    int idx = blockIdx.x * blockDim.x + threadIdx.x;
    if (idx >= P4_ * 68) return;
    int p = idx / 68, c0 = (idx % 68) * 8;
    int bt = p >> 2, n = p & 3;
    union { __half h[8]; uint4 v; } ph;
    float vv[8];
#pragma unroll
    for (int e = 0; e < 8; e++) {
        vv[e] = x[((size_t)bt * C_ + c0 + e) * 4 + n];
        ph.h[e] = __float2half(vv[e]);
    }
    size_t o = (size_t)p * C_ + c0;
    *reinterpret_cast<uint4*>(fb + o) = ph.v;
    float4* d = reinterpret_cast<float4*>(F + o);
    d[0] = make_float4(vv[0], vv[1], vv[2], vv[3]);
    d[1] = make_float4(vv[4], vv[5], vv[6], vv[7]);
}

__global__ void k_build_p(const float* __restrict__ pos, float* __restrict__ P2) {
    int idx = blockIdx.x * blockDim.x + threadIdx.x;
    if (idx >= P4_ * PCH_) return;
    int p = idx / PCH_, k = idx % PCH_;
    P2[idx] = pos[((size_t)(p >> 2) * PCH_ + k) * 4 + (p & 3)];
}

__global__ void k_pos(const float* __restrict__ wpt, const float* __restrict__ P2,
                      float* __restrict__ PP) {
    int idx = blockIdx.x * blockDim.x + threadIdx.x;
    if (idx >= P4_ * CIN_) return;
    int p = idx / CIN_, o = idx % CIN_;
    float acc = 0.f;
#pragma unroll
    for (int k = 0; k < PCH_; k++) acc = fmaf(wpt[k * CIN_ + o], P2[p * PCH_ + k], acc);
    PP[idx] = acc;
}

__global__ void k_h0(const float* __restrict__ AB, const float* __restrict__ PP,
                     const float* __restrict__ bpos, const float* __restrict__ sbn,
                     __half* __restrict__ hh) {
    int idx = blockIdx.x * blockDim.x + threadIdx.x;
    if (idx >= P16_ * 136) return;
    int p16 = idx / 136, o0 = (idx % 136) * 8;
    int bt = p16 >> 4, ij = p16 & 15, i = ij >> 2, j = ij & 3;
    size_t pa = (size_t)(bt * 4 + i) * 2176 + o0;
    size_t pb = (size_t)(bt * 4 + j) * 2176 + 1088 + o0;
    size_t qi = (size_t)(bt * 4 + i) * CIN_ + o0;
    size_t qj = (size_t)(bt * 4 + j) * CIN_ + o0;
    union { __half h[8]; uint4 v; } ph;
#pragma unroll
    for (int e = 0; e < 8; e++) {
        int o = o0 + e;
        float v = fmaxf(fmaf(sbn[o], AB[pa + e] + AB[pb + e], sbn[CIN_ + o]), 0.f);
        v += PP[qi + e] - PP[qj + e] + bpos[o];
        ph.h[e] = __float2half(v);
    }
    *reinterpret_cast<uint4*>(hh + (size_t)p16 * CIN_ + o0) = ph.v;
}

__global__ void k_attl_init(const float* __restrict__ b, float* __restrict__ L) {
    int p = blockIdx.x * blockDim.x + threadIdx.x;
    if (p < P16_) L[p] = b[0];
}

__global__ void k_softmax(const float* __restrict__ L, float* __restrict__ S) {
    int r = blockIdx.x * blockDim.x + threadIdx.x;
    if (r >= P4_) return;
    float l0 = L[r*4], l1 = L[r*4+1], l2 = L[r*4+2], l3 = L[r*4+3];
    float m = fmaxf(fmaxf(l0, l1), fmaxf(l2, l3));
    float e0 = __expf(l0-m), e1 = __expf(l1-m), e2 = __expf(l2-m), e3 = __expf(l3-m);
    float inv = 1.f / (e0+e1+e2+e3);
    S[r*4]=e0*inv; S[r*4+1]=e1*inv; S[r*4+2]=e2*inv; S[r*4+3]=e3*inv;
}

__global__ void k_fuse(const float* __restrict__ F, const float* __restrict__ FST,
                       const float* __restrict__ AG, const float* __restrict__ S,
                       float* __restrict__ out) {
    int idx = blockIdx.x * blockDim.x + threadIdx.x;
    if (idx >= BT_ * 2176) return;
    int bt = idx / 2176, rem = idx % 2176;
    int i = rem / C_, d = rem % C_;
    int ri = bt * 4 + i;
    float acc = F[(size_t)ri * C_ + d];
#pragma unroll
    for (int j = 0; j < 4; j++) {
        float a = S[ri * 4 + j];
        if (j == i) acc = fmaf(FST[(size_t)ri * CIN_ + d], a, acc);
        else acc = fmaf(FST[(size_t)(bt*4+j) * CIN_ + 544 + d] *
                        AG[(size_t)(bt*16+i*4+j) * C_ + d], a, acc);
    }
    out[(size_t)bt * 2176 + d * 4 + i] = acc;
}

// ---------------- HMMA fp16 2-pass GEMM ----------------
// C[m][n] = (Ah+Al)[MP][K] @ B[NP][K]^T, per-row scale rs applied in epilogue.
// EPI: 0 v*rs fp32 | 2 relu->fp16 | 3 fp16resid+relu->fp16 | 4 v*rs+bias fp32 | 5 att-dot atomic
constexpr int TIL = 8192;       // 128 rows x 64 B
constexpr int STG = 3 * TIL;    // Ah|Al|B = 24 KB
constexpr int SMEMB = 4 * STG;  // 96 KB, 4 stages

__device__ __forceinline__ uint32_t swadr(uint32_t base, int row, int c16) {
    return base + row * 64 + ((c16 ^ ((row >> 1) & 3)) << 4);
}

template <int EPI>
__global__ void __launch_bounds__(256, 2)
gemm_mma(const __half* __restrict__ Ahg, const __half* __restrict__ Alg,
         const __half* __restrict__ Bg,
         int K, int KB, int Mreal,
         float* __restrict__ outf, int ldo,
         __half* __restrict__ oh, int ldob,
         const float* __restrict__ sv, const float* __restrict__ tv,
         const float* __restrict__ rs,
         const __half* __restrict__ r16,
         const float* __restrict__ watt) {
    extern __shared__ __half smbuf[];
    const uint32_t sb = smem_u32(smbuf);
    const int tid = threadIdx.x, lane = tid & 31, wid = tid >> 5;
    const int mt = blockIdx.x, nt = blockIdx.y;
    const int wm = (wid >> 2) * 64, wn = (wid & 3) * 32;

    float acc[4][4][4];
#pragma unroll
    for (int a = 0; a < 4; a++)
#pragma unroll
        for (int b = 0; b < 4; b++)
#pragma unroll
            for (int c = 0; c < 4; c++) acc[a][b][c] = 0.f;

    auto load_stage = [&](int s, int kb) {
        uint32_t dstb = sb + s * STG;
        int k0 = kb * 32;
#pragma unroll
        for (int c = 0; c < 2; c++) {
            int q = tid + c * 256;
            int r = q >> 2, ch = q & 3;
            uint32_t d = dstb + r * 64 + ((ch ^ ((r >> 1) & 3)) << 4);
            size_t offA = (size_t)(mt * 128 + r) * K + k0 + ch * 8;
            size_t offB = (size_t)(nt * 128 + r) * K + k0 + ch * 8;
            cp16(d,           Ahg + offA);
            cp16(d + TIL,     Alg + offA);
            cp16(d + 2 * TIL, Bg + offB);
        }
    };

    const int grp = lane >> 3, lrow = lane & 7;

    auto compute_stage = [&](int s) {
        uint32_t base = sb + s * STG;
#pragma unroll
        for (int ks2 = 0; ks2 < 2; ks2++) {
            uint32_t af[4][4], bf[4][2];
            const int cA = ks2 * 2 + (grp >> 1);
            const int cB = ks2 * 2 + (grp & 1);
#pragma unroll
            for (int mi = 0; mi < 4; mi++) {
                int row = wm + mi * 16 + (grp & 1) * 8 + lrow;
                ldsm_x4(af[mi], swadr(base, row, cA));
            }
#pragma unroll
            for (int n2 = 0; n2 < 2; n2++) {
                int row = wn + n2 * 16 + (grp >> 1) * 8 + lrow;
                uint32_t q[4];
                ldsm_x4(q, swadr(base + 2 * TIL, row, cB));
                bf[n2 * 2][0] = q[0]; bf[n2 * 2][1] = q[1];
                bf[n2 * 2 + 1][0] = q[2]; bf[n2 * 2 + 1][1] = q[3];
            }
#pragma unroll
            for (int mi = 0; mi < 4; mi++)
#pragma unroll
                for (int ni = 0; ni < 4; ni++) mma_f16(acc[mi][ni], af[mi], bf[ni]);
#pragma unroll
            for (int mi = 0; mi < 4; mi++) {
                int row = wm + mi * 16 + (grp & 1) * 8 + lrow;
                ldsm_x4(af[mi], swadr(base + TIL, row, cA));
            }
#pragma unroll
            for (int mi = 0; mi < 4; mi++)
#pragma unroll
                for (int ni = 0; ni < 4; ni++) mma_f16(acc[mi][ni], af[mi], bf[ni]);
        }
    };

    load_stage(0, 0); CP_COMMIT();
    load_stage(1, 1); CP_COMMIT();
    load_stage(2, 2); CP_COMMIT();
    for (int kb = 0; kb < KB; kb++) {
        if (kb < KB - 2) { CP_WAIT(2); }
        else if (kb == KB - 2) { CP_WAIT(1); }
        else { CP_WAIT(0); }
        __syncthreads();
        if (kb + 3 < KB) { load_stage((kb + 3) & 3, kb + 3); CP_COMMIT(); }
        compute_stage(kb & 3);
    }
    __syncthreads();

    // transpose through smem
    float* Cs = reinterpret_cast<float*>(smbuf);
#pragma unroll
    for (int mi = 0; mi < 4; mi++)
#pragma unroll
        for (int ni = 0; ni < 4; ni++) {
            int rm = wm + mi * 16 + (lane >> 2);
            int cn = wn + ni * 8 + 2 * (lane & 3);
            Cs[cn * 132 + rm]           = acc[mi][ni][0];
            Cs[(cn + 1) * 132 + rm]     = acc[mi][ni][1];
            Cs[cn * 132 + rm + 8]       = acc[mi][ni][2];
            Cs[(cn + 1) * 132 + rm + 8] = acc[mi][ni][3];
        }
    __syncthreads();

    {
        int nl = tid >> 1, m0 = (tid & 1) * 64;
        int ng = nt * 128 + nl;
        int mg0 = mt * 128 + m0;
        if constexpr (EPI == 5) {
            float wsum = 0.f;
#pragma unroll 8
            for (int j = 0; j < 64; j++) {
                int m = mg0 + j;
                if (m >= Mreal) break;
                float v = Cs[nl * 132 + m0 + j] * rs[m];
                wsum = fmaf(fmaxf(fmaf(sv[m], v, tv[m]), 0.f), watt[m], wsum);
            }
            atomicAdd(&outf[ng], wsum);
        } else if constexpr (EPI == 2 || EPI == 3) {
#pragma unroll
            for (int j0 = 0; j0 < 64; j0 += 8) {
                if (mg0 + j0 >= Mreal) break;
                union { __half h[8]; uint4 v; } ph;
                float rv[8];
                if constexpr (EPI == 3) {
                    uint4 r4 = *reinterpret_cast<const uint4*>(r16 + (size_t)ng * ldob + mg0 + j0);
                    const __half* rr = reinterpret_cast<const __half*>(&r4);
#pragma unroll
                    for (int e = 0; e < 8; e++) rv[e] = __half2float(rr[e]);
                }
#pragma unroll
                for (int e = 0; e < 8; e++) {
                    int m = mg0 + j0 + e;
                    float v = Cs[nl * 132 + m0 + j0 + e] * rs[m];
                    float w = fmaxf(fmaf(sv[m], v, tv[m]), 0.f);
                    if constexpr (EPI == 3) w += rv[e];
                    ph.h[e] = __float2half(w);
                }
                *reinterpret_cast<uint4*>(oh + (size_t)ng * ldob + mg0 + j0) = ph.v;
            }
        } else {
#pragma unroll
            for (int j0 = 0; j0 < 64; j0 += 4) {
                if (mg0 + j0 >= Mreal) break;
                float4 ov;
                float* pv = reinterpret_cast<float*>(&ov);
#pragma unroll
                for (int e = 0; e < 4; e++) {
                    int m = mg0 + j0 + e;
                    float v = Cs[nl * 132 + m0 + j0 + e] * rs[m];
                    if constexpr (EPI == 4) v = v + sv[m];
                    pv[e] = v;
                }
                *reinterpret_cast<float4*>(outf + (size_t)ng * ldo + mg0 + j0) = ov;
            }
        }
    }
}

// ---------------- launch ----------------
extern "C" void kernel_launch(void* const* d_in, const int* in_sizes, int n_in,
                              void* d_out, int out_size) {
    const float *x = (const float*)d_in[0], *pos2d = (const float*)d_in[1];
    const float *w_pos = (const float*)d_in[2], *b_pos = (const float*)d_in[3];
    const float *w_e = (const float*)d_in[4],  *w1 = (const float*)d_in[6];
    const float *w2 = (const float*)d_in[8],   *w_ag = (const float*)d_in[10];
    const float *w_ag_s = (const float*)d_in[12], *b_ag_s = (const float*)d_in[13];
    const float *w_att = (const float*)d_in[14], *w_att_s = (const float*)d_in[16];
    const float *b_att_s = (const float*)d_in[17], *Wsm = (const float*)d_in[18];
    float* out = (float*)d_out;

    float* F32 = nullptr;  __half* H16 = nullptr;
    cudaGetSymbolAddress((void**)&F32, g_F32);
    cudaGetSymbolAddress((void**)&H16, g_H16);

    float *F = F32+OF_F, *P2 = F32+OF_P2, *WPT = F32+OF_WPT, *PP = F32+OF_PP;
    float *AB = F32+OF_AB, *AG = F32+OF_AG, *FST = F32+OF_FST;
    float *ATTL = F32+OF_ATTL, *ATTS = F32+OF_ATTS, *SBN = F32+OF_SBN;
    float *RSWE = F32+OF_RSWE, *RSW1 = F32+OF_RSW1, *RSW2 = F32+OF_RSW2;
    float *RSAG = F32+OF_RSAG, *RSAT = F32+OF_RSAT, *RSWS = F32+OF_RSWS, *RS01 = F32+OF_RS01;

    cudaFuncSetAttribute(gemm_mma<0>, cudaFuncAttributeMaxDynamicSharedMemorySize, SMEMB);
    cudaFuncSetAttribute(gemm_mma<2>, cudaFuncAttributeMaxDynamicSharedMemorySize, SMEMB);
    cudaFuncSetAttribute(gemm_mma<3>, cudaFuncAttributeMaxDynamicSharedMemorySize, SMEMB);
    cudaFuncSetAttribute(gemm_mma<4>, cudaFuncAttributeMaxDynamicSharedMemorySize, SMEMB);
    cudaFuncSetAttribute(gemm_mma<5>, cudaFuncAttributeMaxDynamicSharedMemorySize, SMEMB);

    // launches 1-3, then the big layer-1 GEMM at slot 4 (ncu captures the 4th launch)
    k_build_f<<<(P4_*68+255)/256, 256>>>(x, F, H16+OB_FB);
    k_wscale<<<(2176+7)/8, 256>>>(w_e, 0, 2176, 544, 2176, 3, RSWE);
    k_wprep<<<(2176*68+255)/256, 256>>>(w_e, 0, 2176, 544, 2176, 3, RSWE, H16+OB_WEH, H16+OB_WEL);
    gemm_mma<0><<<dim3(17,32),256,SMEMB>>>(H16+OB_WEH, H16+OB_WEL, H16+OB_FB,
                                           544, 17, 2176, AB, 2176, nullptr, 0,
                                           nullptr, nullptr, RSWE, nullptr, nullptr);

    k_bn_fold<<<(5*CIN_+255)/256, 256>>>((const float*)d_in[5], (const float*)d_in[7],
                                         (const float*)d_in[9], (const float*)d_in[11],
                                         (const float*)d_in[15], SBN);
    k_wposT<<<(PCH_*CIN_+255)/256, 256>>>(w_pos, WPT);
    k_build_p<<<(P4_*PCH_+255)/256, 256>>>(pos2d, P2);
    k_pos<<<(P4_*CIN_+255)/256, 256>>>(WPT, P2, PP);
    k_h0<<<(P16_*136+255)/256, 256>>>(AB, PP, b_pos, SBN, H16+OB_H0);

    // weight preps
    k_wscale<<<(1152+7)/8, 256>>>(w1,    CIN_, 1088, 1088, 1152, 0, RSW1);
    k_wprep<<<(1152*136+255)/256, 256>>>(w1,    CIN_, 1088, 1088, 1152, 0, RSW1, H16+OB_W1H,  H16+OB_W1L);
    k_wscale<<<(1152+7)/8, 256>>>(w2,    CIN_, 1088, 1088, 1152, 0, RSW2);
    k_wprep<<<(1152*136+255)/256, 256>>>(w2,    CIN_, 1088, 1088, 1152, 0, RSW2, H16+OB_W2H,  H16+OB_W2L);
    k_wscale<<<(1152+7)/8, 256>>>(w_ag,  CIN_, 1088, 1088, 1152, 0, RSAG);
    k_wprep<<<(1152*136+255)/256, 256>>>(w_ag,  CIN_, 1088, 1088, 1152, 0, RSAG, H16+OB_WAGH, H16+OB_WAGL);
    k_wscale<<<(1152+7)/8, 256>>>(w_att, CIN_, 1088, 1088, 1152, 0, RSAT);
    k_wprep<<<(1152*136+255)/256, 256>>>(w_att, CIN_, 1088, 1088, 1152, 0, RSAT, H16+OB_WATH, H16+OB_WATL);
    k_wscale<<<(640+7)/8, 256>>>(w_ag_s, CIN_, 544, 1088, 640, 0, RSWS);
    k_wprep<<<(640*136+255)/256, 256>>>(w_ag_s, CIN_, 544, 1088, 640, 0, RSWS, H16+OB_WSH, H16+OB_WSL);
    k_wscale<<<(1152+7)/8, 256>>>(Wsm, 0, 1088, 544, 1152, 2, RS01);
    k_wprep<<<(1152*68+255)/256, 256>>>(Wsm, 0, 1088, 544, 1152, 2, RS01, H16+OB_W01H, H16+OB_W01L);

    // trunk
    gemm_mma<2><<<dim3(9,128),256,SMEMB>>>(H16+OB_W1H, H16+OB_W1L, H16+OB_H0,
                                           1088, 34, 1088, nullptr, 0, H16+OB_H1, CIN_,
                                           SBN+2*CIN_, SBN+3*CIN_, RSW1, nullptr, nullptr);
    gemm_mma<3><<<dim3(9,128),256,SMEMB>>>(H16+OB_W2H, H16+OB_W2L, H16+OB_H1,
                                           1088, 34, 1088, nullptr, 0, H16+OB_H2, CIN_,
                                           SBN+4*CIN_, SBN+5*CIN_, RSW2, H16+OB_H0, nullptr);
    // aggregation branch
    gemm_mma<2><<<dim3(9,128),256,SMEMB>>>(H16+OB_WAGH, H16+OB_WAGL, H16+OB_H2,
                                           1088, 34, 1088, nullptr, 0, H16+OB_G, CIN_,
                                           SBN+6*CIN_, SBN+7*CIN_, RSAG, nullptr, nullptr);
    gemm_mma<4><<<dim3(5,128),256,SMEMB>>>(H16+OB_WSH, H16+OB_WSL, H16+OB_G,
                                           1088, 34, 544, AG, C_, nullptr, 0,
                                           b_ag_s, nullptr, RSWS, nullptr, nullptr);
    // attention branch: logits fused into GEMM epilogue
    k_attl_init<<<(P16_+255)/256, 256>>>(b_att_s, ATTL);
    gemm_mma<5><<<dim3(9,128),256,SMEMB>>>(H16+OB_WATH, H16+OB_WATL, H16+OB_H2,
                                           1088, 34, 1088, ATTL, 0, nullptr, 0,
                                           SBN+8*CIN_, SBN+9*CIN_, RSAT, nullptr, w_att_s);
    k_softmax<<<(P4_+255)/256, 256>>>(ATTL, ATTS);

    // self/transfer stacked: FST = [W0^T; W1^T] @ f
    gemm_mma<0><<<dim3(9,32),256,SMEMB>>>(H16+OB_W01H, H16+OB_W01L, H16+OB_FB,
                                          544, 17, 1088, FST, CIN_, nullptr, 0,
                                          nullptr, nullptr, RS01, nullptr, nullptr);

    k_fuse<<<(BT_*2176+255)/256, 256>>>(F, FST, AG, ATTS, out);
}

// round 8
// speedup vs baseline: 4.1592x; 1.0003x over previous
#include <cuda_runtime.h>
#include <cuda_fp16.h>
#include <stdint.h>
#include <math.h>

namespace fv {
constexpr int C_ = 544, CIN_ = 1088, BT_ = 1024, P4_ = 4096, P16_ = 16384, PCH_ = 34;

// fp32 scratch (elements)
constexpr size_t OF_F    = 0;                              // [P4][544]
constexpr size_t OF_P2   = OF_F    + (size_t)P4_*C_;
constexpr size_t OF_WPT  = OF_P2   + (size_t)P4_*PCH_;
constexpr size_t OF_PP   = OF_WPT  + (size_t)PCH_*CIN_;
constexpr size_t OF_AB   = OF_PP   + (size_t)P4_*CIN_;     // [P4][2176]
constexpr size_t OF_AG   = OF_AB   + (size_t)P4_*2176;     // [P16][544]
constexpr size_t OF_FST  = OF_AG   + (size_t)P16_*C_;      // [P4][1088]
constexpr size_t OF_ATTL = OF_FST  + (size_t)P4_*CIN_;
constexpr size_t OF_ATTS = OF_ATTL + (size_t)P16_;
constexpr size_t OF_SBN  = OF_ATTS + (size_t)P16_;         // [5][2][1088]
constexpr size_t OF_RSWE = OF_SBN  + (size_t)5*2*CIN_;     // 2176
constexpr size_t OF_RSW1 = OF_RSWE + 2176;
constexpr size_t OF_RSW2 = OF_RSW1 + 1152;
constexpr size_t OF_RSAG = OF_RSW2 + 1152;
constexpr size_t OF_RSAT = OF_RSAG + 1152;
constexpr size_t OF_RSWS = OF_RSAT + 1152;                 // 640
constexpr size_t OF_RS01 = OF_RSWS + 640;                  // 1152
constexpr size_t TOT_F32 = OF_RS01 + 1152;

// fp16 row-major scratch [rows][K]
constexpr size_t SZ_FB  = (size_t)P4_ * C_;
constexpr size_t SZ_H   = (size_t)P16_ * CIN_;
constexpr size_t SZ_WE  = (size_t)2176 * 544;
constexpr size_t SZ_WB  = (size_t)1152 * 1088;
constexpr size_t SZ_WS  = (size_t)640 * 1088;
constexpr size_t SZ_W01 = (size_t)1152 * 544;

constexpr size_t OB_FB   = 0;
constexpr size_t OB_H0   = OB_FB   + SZ_FB;
constexpr size_t OB_H1   = OB_H0   + SZ_H;
constexpr size_t OB_H2   = OB_H1   + SZ_H;
constexpr size_t OB_G    = OB_H2   + SZ_H;
constexpr size_t OB_WEH  = OB_G    + SZ_H;
constexpr size_t OB_WEL  = OB_WEH  + SZ_WE;
constexpr size_t OB_W1H  = OB_WEL  + SZ_WE;
constexpr size_t OB_W1L  = OB_W1H  + SZ_WB;
constexpr size_t OB_W2H  = OB_W1L  + SZ_WB;
constexpr size_t OB_W2L  = OB_W2H  + SZ_WB;
constexpr size_t OB_WAGH = OB_W2L  + SZ_WB;
constexpr size_t OB_WAGL = OB_WAGH + SZ_WB;
constexpr size_t OB_WATH = OB_WAGL + SZ_WB;
constexpr size_t OB_WATL = OB_WATH + SZ_WB;
constexpr size_t OB_WSH  = OB_WATL + SZ_WB;
constexpr size_t OB_WSL  = OB_WSH  + SZ_WS;
constexpr size_t OB_W01H = OB_WSL  + SZ_WS;
constexpr size_t OB_W01L = OB_W01H + SZ_W01;
constexpr size_t TOT_H16 = OB_W01L + SZ_W01;
}  // namespace fv

__device__ float  g_F32[fv::TOT_F32];
__device__ __half g_H16[fv::TOT_H16];

using namespace fv;

// ---------------- baseline-PTX helpers ----------------
__device__ __forceinline__ uint32_t smem_u32(const void* p) {
    uint32_t a;
    asm("{ .reg .u64 t; cvta.to.shared.u64 t, %1; cvt.u32.u64 %0, t; }" : "=r"(a) : "l"(p));
    return a;
}
__device__ __forceinline__ void cp16(uint32_t dst, const void* src) {
    asm volatile("cp.async.cg.shared.global [%0], [%1], 16;" :: "r"(dst), "l"(src));
}
#define CP_COMMIT() asm volatile("cp.async.commit_group;" ::: "memory")
#define CP_WAIT(n)  asm volatile("cp.async.wait_group %0;" :: "n"(n) : "memory")

__device__ __forceinline__ void ldsm_x4(uint32_t (&r)[4], uint32_t addr) {
    asm volatile("ldmatrix.sync.aligned.m8n8.x4.shared.b16 {%0,%1,%2,%3}, [%4];"
                 : "=r"(r[0]), "=r"(r[1]), "=r"(r[2]), "=r"(r[3]) : "r"(addr));
}
__device__ __forceinline__ void mma_f16(float (&d)[4], const uint32_t (&a)[4],
                                        const uint32_t (&b)[2]) {
    asm volatile(
        "mma.sync.aligned.m16n8k16.row.col.f32.f16.f16.f32 "
        "{%0,%1,%2,%3}, {%4,%5,%6,%7}, {%8,%9}, {%0,%1,%2,%3};"
        : "+f"(d[0]), "+f"(d[1]), "+f"(d[2]), "+f"(d[3])
        : "r"(a[0]), "r"(a[1]), "r"(a[2]), "r"(a[3]), "r"(b[0]), "r"(b[1]));
}

// ---------------- prep / elementwise ----------------
__global__ void k_bn_fold(const float* __restrict__ b0, const float* __restrict__ b1,
                          const float* __restrict__ b2, const float* __restrict__ b3,
                          const float* __restrict__ b4, float* __restrict__ sbn) {
    int idx = blockIdx.x * blockDim.x + threadIdx.x;
    if (idx >= 5 * CIN_) return;
    int w = idx / CIN_, c = idx % CIN_;
    const float* bn = w == 0 ? b0 : w == 1 ? b1 : w == 2 ? b2 : w == 3 ? b3 : b4;
    float s = bn[c] * rsqrtf(bn[3 * CIN_ + c] + 1e-5f);
    sbn[w * 2 * CIN_ + c] = s;
    sbn[w * 2 * CIN_ + CIN_ + c] = bn[CIN_ + c] - bn[2 * CIN_ + c] * s;
}

__global__ void k_wposT(const float* __restrict__ wpos, float* __restrict__ wpt) {
    int idx = blockIdx.x * blockDim.x + threadIdx.x;
    if (idx >= PCH_ * CIN_) return;
    int k = idx / CIN_, o = idx % CIN_;
    wpt[idx] = wpos[o * PCH_ + k];
}

// weight addressing modes:
// 0: src[r*ld + k]
// 2: stacked Wsm^T: src[(r/544)*295936 + k*544 + (r%544)]
// 3: stacked We:    src[(r%1088)*1088 + (r/1088)*544 + k]
__device__ __forceinline__ float wsrc(const float* src, int ld, int mode, int r, int k) {
    if (mode == 0) return src[(size_t)r * ld + k];
    if (mode == 2) return src[(size_t)(r / 544) * 295936 + (size_t)k * 544 + (r % 544)];
    return src[(size_t)(r % 1088) * 1088 + (size_t)(r / 1088) * 544 + k];
}

__global__ void k_wscale(const float* __restrict__ src, int ld, int Msrc, int K,
                         int MP, int mode, float* __restrict__ rs) {
    int w = threadIdx.x >> 5, lane = threadIdx.x & 31;
    int r = blockIdx.x * 8 + w;
    if (r >= MP) return;
    float mx = 0.f;
    if (r < Msrc)
        for (int k = lane; k < K; k += 32) mx = fmaxf(mx, fabsf(wsrc(src, ld, mode, r, k)));
#pragma unroll
    for (int o = 16; o > 0; o >>= 1) mx = fmaxf(mx, __shfl_xor_sync(0xFFFFFFFFu, mx, o));
    if (lane == 0) {
        int e = 0;
        if (mx > 0.f) frexpf(mx, &e);
        rs[r] = exp2f((float)e);
    }
}

__global__ void k_wprep(const float* __restrict__ src, int ld, int Msrc, int K,
                        int MP, int mode, const float* __restrict__ rs,
                        __half* __restrict__ hi, __half* __restrict__ lo) {
    int K8 = K >> 3;
    int idx = blockIdx.x * blockDim.x + threadIdx.x;
    if (idx >= MP * K8) return;
    int r = idx / K8, k0 = (idx % K8) * 8;
    float inv = 1.0f / rs[r];
    union { __half h[8]; uint4 v; } ph, pl;
#pragma unroll
    for (int e = 0; e < 8; e++) {
        float x = (r < Msrc) ? wsrc(src, ld, mode, r, k0 + e) * inv : 0.f;
        __half h = __float2half(x);
        ph.h[e] = h;
        pl.h[e] = __float2half(x - __half2float(h));
    }
    size_t o = (size_t)r * K + k0;
    *reinterpret_cast<uint4*>(hi + o) = ph.v;
    *reinterpret_cast<uint4*>(lo + o) = pl.v;
}

__global__ void k_build_f(const float* __restrict__ x, float* __restrict__ F,
                          __half* __restrict__ fb) {
    int idx = blockIdx.x * blockDim.x + threadIdx.x;
    if (idx >= P4_ * 68) return;
    int p = idx / 68, c0 = (idx % 68) * 8;
    int bt = p >> 2, n = p & 3;
    union { __half h[8]; uint4 v; } ph;
    float vv[8];
#pragma unroll
    for (int e = 0; e < 8; e++) {
        vv[e] = x[((size_t)bt * C_ + c0 + e) * 4 + n];
        ph.h[e] = __float2half(vv[e]);
    }
    size_t o = (size_t)p * C_ + c0;
    *reinterpret_cast<uint4*>(fb + o) = ph.v;
    float4* d = reinterpret_cast<float4*>(F + o);
    d[0] = make_float4(vv[0], vv[1], vv[2], vv[3]);
    d[1] = make_float4(vv[4], vv[5], vv[6], vv[7]);
}

__global__ void k_build_p(const float* __restrict__ pos, float* __restrict__ P2) {
    int idx = blockIdx.x * blockDim.x + threadIdx.x;
    if (idx >= P4_ * PCH_) return;
    int p = idx / PCH_, k = idx % PCH_;
    P2[idx] = pos[((size_t)(p >> 2) * PCH_ + k) * 4 + (p & 3)];
}

__global__ void k_pos(const float* __restrict__ wpt, const float* __restrict__ P2,
                      float* __restrict__ PP) {
    int idx = blockIdx.x * blockDim.x + threadIdx.x;
    if (idx >= P4_ * CIN_) return;
    int p = idx / CIN_, o = idx % CIN_;
    float acc = 0.f;
#pragma unroll
    for (int k = 0; k < PCH_; k++) acc = fmaf(wpt[k * CIN_ + o], P2[p * PCH_ + k], acc);
    PP[idx] = acc;
}

__global__ void k_h0(const float* __restrict__ AB, const float* __restrict__ PP,
                     const float* __restrict__ bpos, const float* __restrict__ sbn,
                     __half* __restrict__ hh) {
    int idx = blockIdx.x * blockDim.x + threadIdx.x;
    if (idx >= P16_ * 136) return;
    int p16 = idx / 136, o0 = (idx % 136) * 8;
    int bt = p16 >> 4, ij = p16 & 15, i = ij >> 2, j = ij & 3;
    size_t pa = (size_t)(bt * 4 + i) * 2176 + o0;
    size_t pb = (size_t)(bt * 4 + j) * 2176 + 1088 + o0;
    size_t qi = (size_t)(bt * 4 + i) * CIN_ + o0;
    size_t qj = (size_t)(bt * 4 + j) * CIN_ + o0;
    union { __half h[8]; uint4 v; } ph;
#pragma unroll
    for (int e = 0; e < 8; e++) {
        int o = o0 + e;
        float v = fmaxf(fmaf(sbn[o], AB[pa + e] + AB[pb + e], sbn[CIN_ + o]), 0.f);
        v += PP[qi + e] - PP[qj + e] + bpos[o];
        ph.h[e] = __float2half(v);
    }
    *reinterpret_cast<uint4*>(hh + (size_t)p16 * CIN_ + o0) = ph.v;
}

__global__ void k_attl_init(const float* __restrict__ b, float* __restrict__ L) {
    int p = blockIdx.x * blockDim.x + threadIdx.x;
    if (p < P16_) L[p] = b[0];
}

__global__ void k_softmax(const float* __restrict__ L, float* __restrict__ S) {
    int r = blockIdx.x * blockDim.x + threadIdx.x;
    if (r >= P4_) return;
    float l0 = L[r*4], l1 = L[r*4+1], l2 = L[r*4+2], l3 = L[r*4+3];
    float m = fmaxf(fmaxf(l0, l1), fmaxf(l2, l3));
    float e0 = __expf(l0-m), e1 = __expf(l1-m), e2 = __expf(l2-m), e3 = __expf(l3-m);
    float inv = 1.f / (e0+e1+e2+e3);
    S[r*4]=e0*inv; S[r*4+1]=e1*inv; S[r*4+2]=e2*inv; S[r*4+3]=e3*inv;
}

__global__ void k_fuse(const float* __restrict__ F, const float* __restrict__ FST,
                       const float* __restrict__ AG, const float* __restrict__ S,
                       float* __restrict__ out) {
    int idx = blockIdx.x * blockDim.x + threadIdx.x;
    if (idx >= BT_ * 2176) return;
    int bt = idx / 2176, rem = idx % 2176;
    int i = rem / C_, d = rem % C_;
    int ri = bt * 4 + i;
    float acc = F[(size_t)ri * C_ + d];
#pragma unroll
    for (int j = 0; j < 4; j++) {
        float a = S[ri * 4 + j];
        if (j == i) acc = fmaf(FST[(size_t)ri * CIN_ + d], a, acc);
        else acc = fmaf(FST[(size_t)(bt*4+j) * CIN_ + 544 + d] *
                        AG[(size_t)(bt*16+i*4+j) * C_ + d], a, acc);
    }
    out[(size_t)bt * 2176 + d * 4 + i] = acc;
}

// ---------------- HMMA fp16 2-pass GEMM (4x2 warp grid) ----------------
// C[m][n] = (Ah+Al)[MP][K] @ B[NP][K]^T, per-row scale rs applied in epilogue.
// EPI: 0 v*rs fp32 | 2 relu->fp16 | 3 fp16resid+relu->fp16 | 4 v*rs+bias fp32 | 5 att-dot atomic
constexpr int TIL = 8192;       // 128 rows x 64 B
constexpr int STG = 3 * TIL;    // Ah|Al|B = 24 KB
constexpr int SMEMB = 4 * STG;  // 96 KB, 4 stages

__device__ __forceinline__ uint32_t swadr(uint32_t base, int row, int c16) {
    return base + row * 64 + ((c16 ^ ((row >> 1) & 3)) << 4);
}

template <int EPI>
__global__ void __launch_bounds__(256, 2)
gemm_mma(const __half* __restrict__ Ahg, const __half* __restrict__ Alg,
         const __half* __restrict__ Bg,
         int K, int KB, int Mreal,
         float* __restrict__ outf, int ldo,
         __half* __restrict__ oh, int ldob,
         const float* __restrict__ sv, const float* __restrict__ tv,
         const float* __restrict__ rs,
         const __half* __restrict__ r16,
         const float* __restrict__ watt) {
    extern __shared__ __half smbuf[];
    const uint32_t sb = smem_u32(smbuf);
    const int tid = threadIdx.x, lane = tid & 31, wid = tid >> 5;
    const int mt = blockIdx.x, nt = blockIdx.y;
    // 4x2 warp grid: warp tile 32 (M) x 64 (N)
    const int wm = (wid & 3) * 32, wn = (wid >> 2) * 64;

    float acc[2][8][4];
#pragma unroll
    for (int a = 0; a < 2; a++)
#pragma unroll
        for (int b = 0; b < 8; b++)
#pragma unroll
            for (int c = 0; c < 4; c++) acc[a][b][c] = 0.f;

    auto load_stage = [&](int s, int kb) {
        uint32_t dstb = sb + s * STG;
        int k0 = kb * 32;
#pragma unroll
        for (int c = 0; c < 2; c++) {
            int q = tid + c * 256;
            int r = q >> 2, ch = q & 3;
            uint32_t d = dstb + r * 64 + ((ch ^ ((r >> 1) & 3)) << 4);
            size_t offA = (size_t)(mt * 128 + r) * K + k0 + ch * 8;
            size_t offB = (size_t)(nt * 128 + r) * K + k0 + ch * 8;
            cp16(d,           Ahg + offA);
            cp16(d + TIL,     Alg + offA);
            cp16(d + 2 * TIL, Bg + offB);
        }
    };

    const int grp = lane >> 3, lrow = lane & 7;

    auto compute_stage = [&](int s) {
        uint32_t base = sb + s * STG;
#pragma unroll
        for (int ks2 = 0; ks2 < 2; ks2++) {
            uint32_t ah[2][4], al[2][4], bf[8][2];
            const int cA = ks2 * 2 + (grp >> 1);
            const int cB = ks2 * 2 + (grp & 1);
#pragma unroll
            for (int mi = 0; mi < 2; mi++) {
                int row = wm + mi * 16 + (grp & 1) * 8 + lrow;
                ldsm_x4(ah[mi], swadr(base, row, cA));
                ldsm_x4(al[mi], swadr(base + TIL, row, cA));
            }
#pragma unroll
            for (int n2 = 0; n2 < 4; n2++) {
                int row = wn + n2 * 16 + (grp >> 1) * 8 + lrow;
                uint32_t q[4];
                ldsm_x4(q, swadr(base + 2 * TIL, row, cB));
                bf[n2 * 2][0] = q[0]; bf[n2 * 2][1] = q[1];
                bf[n2 * 2 + 1][0] = q[2]; bf[n2 * 2 + 1][1] = q[3];
            }
#pragma unroll
            for (int mi = 0; mi < 2; mi++)
#pragma unroll
                for (int ni = 0; ni < 8; ni++) mma_f16(acc[mi][ni], ah[mi], bf[ni]);
#pragma unroll
            for (int mi = 0; mi < 2; mi++)
#pragma unroll
                for (int ni = 0; ni < 8; ni++) mma_f16(acc[mi][ni], al[mi], bf[ni]);
        }
    };

    load_stage(0, 0); CP_COMMIT();
    load_stage(1, 1); CP_COMMIT();
    load_stage(2, 2); CP_COMMIT();
    for (int kb = 0; kb < KB; kb++) {
        if (kb < KB - 2) { CP_WAIT(2); }
        else if (kb == KB - 2) { CP_WAIT(1); }
        else { CP_WAIT(0); }
        __syncthreads();
        if (kb + 3 < KB) { load_stage((kb + 3) & 3, kb + 3); CP_COMMIT(); }
        compute_stage(kb & 3);
    }
    __syncthreads();

    // transpose through smem
    float* Cs = reinterpret_cast<float*>(smbuf);
#pragma unroll
    for (int mi = 0; mi < 2; mi++)
#pragma unroll
        for (int ni = 0; ni < 8; ni++) {
            int rm = wm + mi * 16 + (lane >> 2);
            int cn = wn + ni * 8 + 2 * (lane & 3);
            Cs[cn * 132 + rm]           = acc[mi][ni][0];
            Cs[(cn + 1) * 132 + rm]     = acc[mi][ni][1];
            Cs[cn * 132 + rm + 8]       = acc[mi][ni][2];
            Cs[(cn + 1) * 132 + rm + 8] = acc[mi][ni][3];
        }
    __syncthreads();

    {
        int nl = tid >> 1, m0 = (tid & 1) * 64;
        int ng = nt * 128 + nl;
        int mg0 = mt * 128 + m0;
        if constexpr (EPI == 5) {
            float wsum = 0.f;
#pragma unroll 8
            for (int j = 0; j < 64; j++) {
                int m = mg0 + j;
                if (m >= Mreal) break;
                float v = Cs[nl * 132 + m0 + j] * rs[m];
                wsum = fmaf(fmaxf(fmaf(sv[m], v, tv[m]), 0.f), watt[m], wsum);
            }
            atomicAdd(&outf[ng], wsum);
        } else if constexpr (EPI == 2 || EPI == 3) {
#pragma unroll
            for (int j0 = 0; j0 < 64; j0 += 8) {
                if (mg0 + j0 >= Mreal) break;
                union { __half h[8]; uint4 v; } ph;
                float rv[8];
                if constexpr (EPI == 3) {
                    uint4 r4 = *reinterpret_cast<const uint4*>(r16 + (size_t)ng * ldob + mg0 + j0);
                    const __half* rr = reinterpret_cast<const __half*>(&r4);
#pragma unroll
                    for (int e = 0; e < 8; e++) rv[e] = __half2float(rr[e]);
                }
#pragma unroll
                for (int e = 0; e < 8; e++) {
                    int m = mg0 + j0 + e;
                    float v = Cs[nl * 132 + m0 + j0 + e] * rs[m];
                    float w = fmaxf(fmaf(sv[m], v, tv[m]), 0.f);
                    if constexpr (EPI == 3) w += rv[e];
                    ph.h[e] = __float2half(w);
                }
                *reinterpret_cast<uint4*>(oh + (size_t)ng * ldob + mg0 + j0) = ph.v;
            }
        } else {
#pragma unroll
            for (int j0 = 0; j0 < 64; j0 += 4) {
                if (mg0 + j0 >= Mreal) break;
                float4 ov;
                float* pv = reinterpret_cast<float*>(&ov);
#pragma unroll
                for (int e = 0; e < 4; e++) {
                    int m = mg0 + j0 + e;
                    float v = Cs[nl * 132 + m0 + j0 + e] * rs[m];
                    if constexpr (EPI == 4) v = v + sv[m];
                    pv[e] = v;
                }
                *reinterpret_cast<float4*>(outf + (size_t)ng * ldo + mg0 + j0) = ov;
            }
        }
    }
}

// ---------------- launch ----------------
extern "C" void kernel_launch(void* const* d_in, const int* in_sizes, int n_in,
                              void* d_out, int out_size) {
    const float *x = (const float*)d_in[0], *pos2d = (const float*)d_in[1];
    const float *w_pos = (const float*)d_in[2], *b_pos = (const float*)d_in[3];
    const float *w_e = (const float*)d_in[4],  *w1 = (const float*)d_in[6];
    const float *w2 = (const float*)d_in[8],   *w_ag = (const float*)d_in[10];
    const float *w_ag_s = (const float*)d_in[12], *b_ag_s = (const float*)d_in[13];
    const float *w_att = (const float*)d_in[14], *w_att_s = (const float*)d_in[16];
    const float *b_att_s = (const float*)d_in[17], *Wsm = (const float*)d_in[18];
    float* out = (float*)d_out;

    float* F32 = nullptr;  __half* H16 = nullptr;
    cudaGetSymbolAddress((void**)&F32, g_F32);
    cudaGetSymbolAddress((void**)&H16, g_H16);

    float *F = F32+OF_F, *P2 = F32+OF_P2, *WPT = F32+OF_WPT, *PP = F32+OF_PP;
    float *AB = F32+OF_AB, *AG = F32+OF_AG, *FST = F32+OF_FST;
    float *ATTL = F32+OF_ATTL, *ATTS = F32+OF_ATTS, *SBN = F32+OF_SBN;
    float *RSWE = F32+OF_RSWE, *RSW1 = F32+OF_RSW1, *RSW2 = F32+OF_RSW2;
    float *RSAG = F32+OF_RSAG, *RSAT = F32+OF_RSAT, *RSWS = F32+OF_RSWS, *RS01 = F32+OF_RS01;

    cudaFuncSetAttribute(gemm_mma<0>, cudaFuncAttributeMaxDynamicSharedMemorySize, SMEMB);
    cudaFuncSetAttribute(gemm_mma<2>, cudaFuncAttributeMaxDynamicSharedMemorySize, SMEMB);
    cudaFuncSetAttribute(gemm_mma<3>, cudaFuncAttributeMaxDynamicSharedMemorySize, SMEMB);
    cudaFuncSetAttribute(gemm_mma<4>, cudaFuncAttributeMaxDynamicSharedMemorySize, SMEMB);
    cudaFuncSetAttribute(gemm_mma<5>, cudaFuncAttributeMaxDynamicSharedMemorySize, SMEMB);

    // launches 1-3, then the big layer-1 GEMM at slot 4 (ncu captures the 4th launch)
    k_build_f<<<(P4_*68+255)/256, 256>>>(x, F, H16+OB_FB);
    k_wscale<<<(2176+7)/8, 256>>>(w_e, 0, 2176, 544, 2176, 3, RSWE);
    k_wprep<<<(2176*68+255)/256, 256>>>(w_e, 0, 2176, 544, 2176, 3, RSWE, H16+OB_WEH, H16+OB_WEL);
    gemm_mma<0><<<dim3(17,32),256,SMEMB>>>(H16+OB_WEH, H16+OB_WEL, H16+OB_FB,
                                           544, 17, 2176, AB, 2176, nullptr, 0,
                                           nullptr, nullptr, RSWE, nullptr, nullptr);

    k_bn_fold<<<(5*CIN_+255)/256, 256>>>((const float*)d_in[5], (const float*)d_in[7],
                                         (const float*)d_in[9], (const float*)d_in[11],
                                         (const float*)d_in[15], SBN);
    k_wposT<<<(PCH_*CIN_+255)/256, 256>>>(w_pos, WPT);
    k_build_p<<<(P4_*PCH_+255)/256, 256>>>(pos2d, P2);
    k_pos<<<(P4_*CIN_+255)/256, 256>>>(WPT, P2, PP);
    k_h0<<<(P16_*136+255)/256, 256>>>(AB, PP, b_pos, SBN, H16+OB_H0);

    // weight preps
    k_wscale<<<(1152+7)/8, 256>>>(w1,    CIN_, 1088, 1088, 1152, 0, RSW1);
    k_wprep<<<(1152*136+255)/256, 256>>>(w1,    CIN_, 1088, 1088, 1152, 0, RSW1, H16+OB_W1H,  H16+OB_W1L);
    k_wscale<<<(1152+7)/8, 256>>>(w2,    CIN_, 1088, 1088, 1152, 0, RSW2);
    k_wprep<<<(1152*136+255)/256, 256>>>(w2,    CIN_, 1088, 1088, 1152, 0, RSW2, H16+OB_W2H,  H16+OB_W2L);
    k_wscale<<<(1152+7)/8, 256>>>(w_ag,  CIN_, 1088, 1088, 1152, 0, RSAG);
    k_wprep<<<(1152*136+255)/256, 256>>>(w_ag,  CIN_, 1088, 1088, 1152, 0, RSAG, H16+OB_WAGH, H16+OB_WAGL);
    k_wscale<<<(1152+7)/8, 256>>>(w_att, CIN_, 1088, 1088, 1152, 0, RSAT);
    k_wprep<<<(1152*136+255)/256, 256>>>(w_att, CIN_, 1088, 1088, 1152, 0, RSAT, H16+OB_WATH, H16+OB_WATL);
    k_wscale<<<(640+7)/8, 256>>>(w_ag_s, CIN_, 544, 1088, 640, 0, RSWS);
    k_wprep<<<(640*136+255)/256, 256>>>(w_ag_s, CIN_, 544, 1088, 640, 0, RSWS, H16+OB_WSH, H16+OB_WSL);
    k_wscale<<<(1152+7)/8, 256>>>(Wsm, 0, 1088, 544, 1152, 2, RS01);
    k_wprep<<<(1152*68+255)/256, 256>>>(Wsm, 0, 1088, 544, 1152, 2, RS01, H16+OB_W01H, H16+OB_W01L);

    // trunk
    gemm_mma<2><<<dim3(9,128),256,SMEMB>>>(H16+OB_W1H, H16+OB_W1L, H16+OB_H0,
                                           1088, 34, 1088, nullptr, 0, H16+OB_H1, CIN_,
                                           SBN+2*CIN_, SBN+3*CIN_, RSW1, nullptr, nullptr);
    gemm_mma<3><<<dim3(9,128),256,SMEMB>>>(H16+OB_W2H, H16+OB_W2L, H16+OB_H1,
                                           1088, 34, 1088, nullptr, 0, H16+OB_H2, CIN_,
                                           SBN+4*CIN_, SBN+5*CIN_, RSW2, H16+OB_H0, nullptr);
    // aggregation branch
    gemm_mma<2><<<dim3(9,128),256,SMEMB>>>(H16+OB_WAGH, H16+OB_WAGL, H16+OB_H2,
                                           1088, 34, 1088, nullptr, 0, H16+OB_G, CIN_,
                                           SBN+6*CIN_, SBN+7*CIN_, RSAG, nullptr, nullptr);
    gemm_mma<4><<<dim3(5,128),256,SMEMB>>>(H16+OB_WSH, H16+OB_WSL, H16+OB_G,
                                           1088, 34, 544, AG, C_, nullptr, 0,
                                           b_ag_s, nullptr, RSWS, nullptr, nullptr);
    // attention branch: logits fused into GEMM epilogue
    k_attl_init<<<(P16_+255)/256, 256>>>(b_att_s, ATTL);
    gemm_mma<5><<<dim3(9,128),256,SMEMB>>>(H16+OB_WATH, H16+OB_WATL, H16+OB_H2,
                                           1088, 34, 1088, ATTL, 0, nullptr, 0,
                                           SBN+8*CIN_, SBN+9*CIN_, RSAT, nullptr, w_att_s);
    k_softmax<<<(P4_+255)/256, 256>>>(ATTL, ATTS);

    // self/transfer stacked: FST = [W0^T; W1^T] @ f
    gemm_mma<0><<<dim3(9,32),256,SMEMB>>>(H16+OB_W01H, H16+OB_W01L, H16+OB_FB,
                                          544, 17, 1088, FST, CIN_, nullptr, 0,
                                          nullptr, nullptr, RS01, nullptr, nullptr);

    k_fuse<<<(BT_*2176+255)/256, 256>>>(F, FST, AG, ATTS, out);
}